// round 3
// baseline (speedup 1.0000x reference)
#include <cuda_runtime.h>
#include <math.h>

#define HDIM 72
#define NSEQ 256
#define BATCH 16
#define ROWS 4096          // BATCH*NSEQ
#define PAIRS 1048576      // ROWS*NSEQ
#define SDIM 13
#define TPITCH 73

// ---------------- device scratch (static, no runtime alloc) ----------------
__device__ float  d_A [ROWS*HDIM];
__device__ float  d_Bm[ROWS*HDIM];
__device__ float2 d_G [PAIRS];
__device__ float  d_Rn[ROWS];
__device__ float  d_Rd[ROWS];
__device__ float  d_S5[5];          // Sn, Sd, Snn, Sdd, Snd
__device__ float  d_SA[BATCH*HDIM];
__device__ float  d_SB[BATCH*HDIM];
__device__ float  d_T6[6*HDIM];     // TAA,TBB,TAn,TAd,TBn,TBd
__device__ float  d_bn1[2*HDIM];    // scale, shift
__device__ float  d_magg[ROWS*HDIM];
__device__ float  d_y0 [ROWS*HDIM];
__device__ float  d_bn2[2*HDIM];

__device__ __forceinline__ float psif(float x){
    return copysignf(log1pf(fabsf(x)), x);
}
__device__ __forceinline__ float wsum(float v){
    v += __shfl_xor_sync(0xffffffffu, v, 16);
    v += __shfl_xor_sync(0xffffffffu, v, 8);
    v += __shfl_xor_sync(0xffffffffu, v, 4);
    v += __shfl_xor_sync(0xffffffffu, v, 2);
    v += __shfl_xor_sync(0xffffffffu, v, 1);
    return v;
}

// ---------------- zero accumulators (graph replays!) ----------------
__global__ void k_zero(){
    int t = threadIdx.x;
    if (t < 5) d_S5[t] = 0.f;
    for (int i = t; i < 6*HDIM; i += blockDim.x) d_T6[i] = 0.f;
}

// ---------------- geometry: n,d per pair + scalar moments ----------------
__global__ void k_geom(const float* __restrict__ p){
    int i = blockIdx.x, b = blockIdx.y;
    int row = b*NSEQ + i;
    int j = threadIdx.x;
    __shared__ float4 pi4s;
    __shared__ float red[8][5];
    if (j == 0) pi4s = reinterpret_cast<const float4*>(p)[row];
    __syncthreads();
    float4 pi = pi4s;
    float4 pj = reinterpret_cast<const float4*>(p)[b*NSEQ + j];
    float d0=pi.x-pj.x, d1=pi.y-pj.y, d2=pi.z-pj.z, d3=pi.w-pj.w;
    float n  = psif(d1*d1 + d2*d2 + d3*d3 - d0*d0);
    float dt = psif(pi.x*pj.x - pi.y*pj.y - pi.z*pj.z - pi.w*pj.w);
    d_G[row*NSEQ + j] = make_float2(n, dt);
    float v0=wsum(n), v1=wsum(dt), v2=wsum(n*n), v3=wsum(dt*dt), v4=wsum(n*dt);
    int lane = j & 31, w = j >> 5;
    if (lane==0){ red[w][0]=v0; red[w][1]=v1; red[w][2]=v2; red[w][3]=v3; red[w][4]=v4; }
    __syncthreads();
    if (j == 0){
        float s0=0,s1=0,s2=0,s3=0,s4=0;
        for (int q=0;q<8;q++){ s0+=red[q][0]; s1+=red[q][1]; s2+=red[q][2]; s3+=red[q][3]; s4+=red[q][4]; }
        d_Rn[row]=s0; d_Rd[row]=s1;
        atomicAdd(&d_S5[0], s0); atomicAdd(&d_S5[1], s1);
        atomicAdd(&d_S5[2], s2); atomicAdd(&d_S5[3], s3); atomicAdd(&d_S5[4], s4);
    }
}

// ---------------- A = h@We1[0:72], B = h@We1[72:144] ----------------
__global__ void k_AB(const float* __restrict__ h, const float* __restrict__ We1){
    __shared__ float Ws[144*HDIM];
    __shared__ float hs[HDIM];
    int row = blockIdx.x;
    int t = threadIdx.x;   // 144 threads
    for (int idx=t; idx<144*HDIM; idx+=144) Ws[idx] = We1[idx];
    if (t < HDIM) hs[t] = h[row*HDIM + t];
    __syncthreads();
    if (t < HDIM){
        float acc = 0.f;
        #pragma unroll 8
        for (int k=0;k<HDIM;k++) acc = fmaf(hs[k], Ws[k*HDIM + t], acc);
        d_A[row*HDIM + t] = acc;
    } else {
        int c = t - HDIM;
        float acc = 0.f;
        #pragma unroll 8
        for (int k=0;k<HDIM;k++) acc = fmaf(hs[k], Ws[(HDIM+k)*HDIM + c], acc);
        d_Bm[row*HDIM + c] = acc;
    }
}

// ---------------- per-channel moments of A,B ----------------
__global__ void k_mom(){
    int c = blockIdx.x, b = blockIdx.y;
    int t = threadIdx.x; // 256
    int r = b*NSEQ + t;
    float a  = d_A [r*HDIM + c];
    float bb = d_Bm[r*HDIM + c];
    float rn = d_Rn[r], rd = d_Rd[r];
    float v[8] = { a, bb, a*a, bb*bb, a*rn, a*rd, bb*rn, bb*rd };
    __shared__ float red[8][8];
    int lane = t & 31, w = t >> 5;
    #pragma unroll
    for (int q=0;q<8;q++){
        float s = wsum(v[q]);
        if (lane==0) red[w][q] = s;
    }
    __syncthreads();
    if (t == 0){
        float s[8];
        #pragma unroll
        for (int q=0;q<8;q++){ s[q]=0.f; for (int ww=0;ww<8;ww++) s[q]+=red[ww][q]; }
        d_SA[b*HDIM + c] = s[0];
        d_SB[b*HDIM + c] = s[1];
        atomicAdd(&d_T6[0*HDIM + c], s[2]);
        atomicAdd(&d_T6[1*HDIM + c], s[3]);
        atomicAdd(&d_T6[2*HDIM + c], s[4]);
        atomicAdd(&d_T6[3*HDIM + c], s[5]);
        atomicAdd(&d_T6[4*HDIM + c], s[6]);
        atomicAdd(&d_T6[5*HDIM + c], s[7]);
    }
}

// ---------------- finalize BN1 scale/shift (exact algebra) ----------------
__global__ void k_bn1(const float* __restrict__ We1, const float* __restrict__ g1,
                      const float* __restrict__ b1){
    int c = threadIdx.x;
    if (c >= HDIM) return;
    float r1 = We1[144*HDIM + c], r2 = We1[145*HDIM + c];
    float SAt=0.f, SBt=0.f, cross=0.f;
    for (int b=0;b<BATCH;b++){
        float sa = d_SA[b*HDIM+c], sb = d_SB[b*HDIM+c];
        SAt += sa; SBt += sb; cross += sa*sb;
    }
    float Sn=d_S5[0], Sd=d_S5[1], Snn=d_S5[2], Sdd=d_S5[3], Snd=d_S5[4];
    float sumx  = 256.f*(SAt + SBt) + r1*Sn + r2*Sd;
    float sumx2 = 256.f*(d_T6[c] + d_T6[HDIM+c])
                + r1*r1*Snn + r2*r2*Sdd
                + 2.f*cross
                + 2.f*r1*(d_T6[2*HDIM+c] + d_T6[4*HDIM+c])
                + 2.f*r2*(d_T6[3*HDIM+c] + d_T6[5*HDIM+c])
                + 2.f*r1*r2*Snd;
    const float P = 1048576.f;
    float mu  = sumx / P;
    float var = sumx2 / P - mu*mu;
    float sc  = g1[c] * rsqrtf(var + 1e-5f);
    d_bn1[c]        = sc;
    d_bn1[HDIM + c] = b1[c] - mu*sc;
}

// ---------------- main pairwise kernel ----------------
struct MainSmem {
    float  T[128][TPITCH];
    float  We2[HDIM*HDIM];
    float  Wx1[HDIM*HDIM];
    float  A[HDIM], r1[HDIM], r2[HDIM], sc[HDIM], sh[HDIM];
    float  be2v[HDIM], bx1v[HDIM], Wmv[HDIM], Wx2v[HDIM], mg[HDIM];
    float2 nd[128];
    float  wv[128];
    float  xw[128];
    float  pis[4];
    float  aggred[4][4];
    float  bmv;
};

__global__ __launch_bounds__(256, 2) void k_main(
    const float* __restrict__ p,   const float* __restrict__ We1,
    const float* __restrict__ We2, const float* __restrict__ be2,
    const float* __restrict__ Wm,  const float* __restrict__ bm,
    const float* __restrict__ Wx1, const float* __restrict__ bx1,
    const float* __restrict__ Wx2, float* __restrict__ out_p)
{
    extern __shared__ unsigned char smraw[];
    MainSmem* S = reinterpret_cast<MainSmem*>(smraw);
    int i = blockIdx.x, b = blockIdx.y;
    int row = b*NSEQ + i;
    int tid = threadIdx.x;
    for (int idx=tid; idx<HDIM*HDIM; idx+=256){
        S->We2[idx] = We2[idx];
        S->Wx1[idx] = Wx1[idx];
    }
    if (tid < HDIM){
        S->A[tid]    = d_A[row*HDIM + tid];
        S->r1[tid]   = We1[144*HDIM + tid];
        S->r2[tid]   = We1[145*HDIM + tid];
        S->sc[tid]   = d_bn1[tid];
        S->sh[tid]   = d_bn1[HDIM + tid];
        S->be2v[tid] = be2[tid];
        S->bx1v[tid] = bx1[tid];
        S->Wmv[tid]  = Wm[tid];
        S->Wx2v[tid] = Wx2[tid];
        S->mg[tid]   = 0.f;
    }
    if (tid < 4)  S->pis[tid] = p[row*4 + tid];
    if (tid == 0) S->bmv = bm[0];
    __syncthreads();

    int cg = tid & 7, rg = tid >> 3;
    int r0 = rg*4, c0 = cg*9;
    float agg0=0.f, agg1=0.f, agg2=0.f, agg3=0.f;

    for (int tile=0; tile<2; ++tile){
        int j0 = tile*128;
        if (tid < 128) S->nd[tid] = d_G[row*NSEQ + j0 + tid];
        __syncthreads();
        {   // build T = relu(BN(x)), x = A_i + B_j + n r1 + d r2
            const float* Bb = d_Bm + (b*NSEQ + j0)*HDIM;
            for (int idx=tid; idx<128*HDIM; idx+=256){
                int j = idx / HDIM;
                int c = idx - j*HDIM;
                float2 nd = S->nd[j];
                float v = S->A[c] + Bb[idx] + nd.x*S->r1[c] + nd.y*S->r2[c];
                v = fmaf(v, S->sc[c], S->sh[c]);
                S->T[j][c] = fmaxf(v, 0.f);
            }
        }
        __syncthreads();
        // GEMM1: M = relu(T @ We2 + be2)
        float acc[4][9];
        #pragma unroll
        for (int q=0;q<4;q++)
            #pragma unroll
            for (int m=0;m<9;m++) acc[q][m]=0.f;
        {
            const float* T0 = &S->T[r0][0];
            const float* Wc = S->We2 + c0;
            #pragma unroll 8
            for (int k=0;k<HDIM;k++){
                float a0=T0[k], a1=T0[TPITCH+k], a2=T0[2*TPITCH+k], a3=T0[3*TPITCH+k];
                #pragma unroll
                for (int m=0;m<9;m++){
                    float w = Wc[k*HDIM + m];
                    acc[0][m]=fmaf(a0,w,acc[0][m]);
                    acc[1][m]=fmaf(a1,w,acc[1][m]);
                    acc[2][m]=fmaf(a2,w,acc[2][m]);
                    acc[3][m]=fmaf(a3,w,acc[3][m]);
                }
            }
        }
        __syncthreads();   // all reads of T done
        #pragma unroll
        for (int q=0;q<4;q++)
            #pragma unroll
            for (int m=0;m<9;m++)
                S->T[r0+q][c0+m] = fmaxf(acc[q][m] + S->be2v[c0+m], 0.f);
        __syncthreads();
        // gate w = sigmoid(m . Wm + bm)
        if (tid < 128){
            float dot = 0.f;
            #pragma unroll 8
            for (int c=0;c<HDIM;c++) dot = fmaf(S->T[tid][c], S->Wmv[c], dot);
            S->wv[tid] = 1.f / (1.f + expf(-(dot + S->bmv)));
        }
        __syncthreads();
        // wm = m * w (in place)
        for (int idx=tid; idx<128*HDIM; idx+=256){
            int j = idx / HDIM;
            int c = idx - j*HDIM;
            S->T[j][c] *= S->wv[j];
        }
        __syncthreads();
        // GEMM2: U = relu(wm @ Wx1 + bx1); xw = U . Wx2
        #pragma unroll
        for (int q=0;q<4;q++)
            #pragma unroll
            for (int m=0;m<9;m++) acc[q][m]=0.f;
        {
            const float* T0 = &S->T[r0][0];
            const float* Wc = S->Wx1 + c0;
            #pragma unroll 8
            for (int k=0;k<HDIM;k++){
                float a0=T0[k], a1=T0[TPITCH+k], a2=T0[2*TPITCH+k], a3=T0[3*TPITCH+k];
                #pragma unroll
                for (int m=0;m<9;m++){
                    float w = Wc[k*HDIM + m];
                    acc[0][m]=fmaf(a0,w,acc[0][m]);
                    acc[1][m]=fmaf(a1,w,acc[1][m]);
                    acc[2][m]=fmaf(a2,w,acc[2][m]);
                    acc[3][m]=fmaf(a3,w,acc[3][m]);
                }
            }
        }
        #pragma unroll
        for (int q=0;q<4;q++){
            float pq = 0.f;
            #pragma unroll
            for (int m=0;m<9;m++){
                float u = fmaxf(acc[q][m] + S->bx1v[c0+m], 0.f);
                pq = fmaf(u, S->Wx2v[c0+m], pq);
            }
            pq += __shfl_xor_sync(0xffffffffu, pq, 1);
            pq += __shfl_xor_sync(0xffffffffu, pq, 2);
            pq += __shfl_xor_sync(0xffffffffu, pq, 4);
            if (cg == 0) S->xw[r0+q] = pq;
        }
        __syncthreads();
        // aggs (clip(p_diff*xw)) and magg (sum wm over j)
        if (tid < 128){
            float x = S->xw[tid];
            float4 pj = reinterpret_cast<const float4*>(p)[b*NSEQ + j0 + tid];
            agg0 += fminf(fmaxf((S->pis[0]-pj.x)*x, -100.f), 100.f);
            agg1 += fminf(fmaxf((S->pis[1]-pj.y)*x, -100.f), 100.f);
            agg2 += fminf(fmaxf((S->pis[2]-pj.z)*x, -100.f), 100.f);
            agg3 += fminf(fmaxf((S->pis[3]-pj.w)*x, -100.f), 100.f);
        }
        if (tid < HDIM){
            float ssum = 0.f;
            #pragma unroll 8
            for (int j=0;j<128;j++) ssum += S->T[j][tid];
            S->mg[tid] += ssum;
        }
        __syncthreads();
    }
    if (tid < HDIM) d_magg[row*HDIM + tid] = S->mg[tid];
    if (tid < 128){
        float s0=wsum(agg0), s1=wsum(agg1), s2=wsum(agg2), s3=wsum(agg3);
        int lane = tid & 31, w = tid >> 5;
        if (lane==0){ S->aggred[w][0]=s0; S->aggred[w][1]=s1; S->aggred[w][2]=s2; S->aggred[w][3]=s3; }
    }
    __syncthreads();
    if (tid < 4){
        float s = S->aggred[0][tid]+S->aggred[1][tid]+S->aggred[2][tid]+S->aggred[3][tid];
        out_p[row*4 + tid] = S->pis[tid] + (s * (1.f/256.f)) * 0.001f;
    }
}

// ---------------- h-path: y0 = [h,magg,s] @ Wh1 + bh1 ----------------
__global__ void k_y0(const float* __restrict__ h, const float* __restrict__ s,
                     const float* __restrict__ Wh1, const float* __restrict__ bh1){
    __shared__ float hin[2*HDIM + SDIM];
    int row = blockIdx.x;
    int t = threadIdx.x; // 160
    if (t < HDIM)               hin[t] = h[row*HDIM + t];
    else if (t < 2*HDIM)        hin[t] = d_magg[row*HDIM + (t - HDIM)];
    else if (t < 2*HDIM + SDIM) hin[t] = s[row*SDIM + (t - 2*HDIM)];
    __syncthreads();
    if (t < HDIM){
        float acc = bh1[t];
        #pragma unroll 8
        for (int k=0;k<2*HDIM+SDIM;k++) acc = fmaf(hin[k], Wh1[k*HDIM + t], acc);
        d_y0[row*HDIM + t] = acc;
    }
}

__global__ void k_bn2(const float* __restrict__ gh, const float* __restrict__ bh){
    int c = blockIdx.x;
    int t = threadIdx.x; // 256
    float sum=0.f, sq=0.f;
    for (int r=t; r<ROWS; r+=256){
        float v = d_y0[r*HDIM + c];
        sum += v; sq += v*v;
    }
    __shared__ float red[8][2];
    float s0 = wsum(sum), s1 = wsum(sq);
    int lane=t&31, w=t>>5;
    if (lane==0){ red[w][0]=s0; red[w][1]=s1; }
    __syncthreads();
    if (t==0){
        float a=0.f,bb=0.f;
        for (int q=0;q<8;q++){ a+=red[q][0]; bb+=red[q][1]; }
        float mu  = a / 4096.f;
        float var = bb / 4096.f - mu*mu;
        float sc  = gh[c] * rsqrtf(var + 1e-5f);
        d_bn2[c]        = sc;
        d_bn2[HDIM + c] = bh[c] - mu*sc;
    }
}

__global__ void k_hout(const float* __restrict__ h, const float* __restrict__ Wh2,
                       const float* __restrict__ bh2, float* __restrict__ out_h){
    __shared__ float yr[HDIM];
    __shared__ float W[HDIM*HDIM];
    int row = blockIdx.x;
    int t = threadIdx.x; // 128
    if (t < HDIM) yr[t] = fmaxf(fmaf(d_y0[row*HDIM+t], d_bn2[t], d_bn2[HDIM+t]), 0.f);
    for (int idx=t; idx<HDIM*HDIM; idx+=128) W[idx] = Wh2[idx];
    __syncthreads();
    if (t < HDIM){
        float acc = bh2[t];
        #pragma unroll 8
        for (int k=0;k<HDIM;k++) acc = fmaf(yr[k], W[k*HDIM + t], acc);
        out_h[row*HDIM + t] = h[row*HDIM + t] + acc;
    }
}

// ---------------- launch ----------------
extern "C" void kernel_launch(void* const* d_in, const int* in_sizes, int n_in,
                              void* d_out, int out_size){
    const float* h   = (const float*)d_in[0];
    const float* p   = (const float*)d_in[1];
    const float* s   = (const float*)d_in[2];
    const float* We1 = (const float*)d_in[3];
    const float* g1  = (const float*)d_in[4];
    const float* b1  = (const float*)d_in[5];
    const float* We2 = (const float*)d_in[6];
    const float* be2 = (const float*)d_in[7];
    const float* Wm  = (const float*)d_in[8];
    const float* bm  = (const float*)d_in[9];
    const float* Wx1 = (const float*)d_in[10];
    const float* bx1 = (const float*)d_in[11];
    const float* Wx2 = (const float*)d_in[12];
    const float* Wh1 = (const float*)d_in[13];
    const float* bh1 = (const float*)d_in[14];
    const float* gh  = (const float*)d_in[15];
    const float* bh  = (const float*)d_in[16];
    const float* Wh2 = (const float*)d_in[17];
    const float* bh2 = (const float*)d_in[18];
    float* out   = (float*)d_out;
    float* out_h = out;                 // (B,N,H) first
    float* out_p = out + ROWS*HDIM;     // then (B,N,4)

    int smsz = (int)sizeof(MainSmem);
    cudaFuncSetAttribute(k_main, cudaFuncAttributeMaxDynamicSharedMemorySize, smsz);

    k_zero<<<1, 512>>>();
    k_geom<<<dim3(NSEQ, BATCH), NSEQ>>>(p);
    k_AB  <<<ROWS, 144>>>(h, We1);
    k_mom <<<dim3(HDIM, BATCH), 256>>>();
    k_bn1 <<<1, HDIM>>>(We1, g1, b1);
    k_main<<<dim3(NSEQ, BATCH), 256, smsz>>>(p, We1, We2, be2, Wm, bm, Wx1, bx1, Wx2, out_p);
    k_y0  <<<ROWS, 160>>>(h, s, Wh1, bh1);
    k_bn2 <<<HDIM, 256>>>(gh, bh);
    k_hout<<<ROWS, 128>>>(h, Wh2, bh2, out_h);
}

// round 7
// speedup vs baseline: 2.0718x; 2.0718x over previous
#include <cuda_runtime.h>
#include <math.h>
#include <stdint.h>

#define HDIM 72
#define NSEQ 256
#define BATCH 16
#define ROWS 4096          // BATCH*NSEQ
#define PAIRS 1048576      // ROWS*NSEQ
#define SDIM 13
#define TP 76              // T smem pitch (floats): >=72, pitch%32=12 -> conflict-free A frags

// ---------------- device scratch (static, no runtime alloc) ----------------
__device__ float  d_A [ROWS*HDIM];
__device__ float  d_Bm[ROWS*HDIM];
__device__ float2 d_G [PAIRS];
__device__ float  d_Rn[ROWS];
__device__ float  d_Rd[ROWS];
__device__ float  d_S5[5];          // Sn, Sd, Snn, Sdd, Snd
__device__ float  d_SA[BATCH*HDIM];
__device__ float  d_SB[BATCH*HDIM];
__device__ float  d_T6[6*HDIM];     // TAA,TBB,TAn,TAd,TBn,TBd
__device__ float  d_bn1[2*HDIM];    // scale, shift
__device__ float  d_magg[ROWS*HDIM];
__device__ float  d_y0 [ROWS*HDIM];
__device__ float  d_bn2[2*HDIM];

__device__ __forceinline__ float psif(float x){
    return copysignf(log1pf(fabsf(x)), x);
}
__device__ __forceinline__ float wsum(float v){
    v += __shfl_xor_sync(0xffffffffu, v, 16);
    v += __shfl_xor_sync(0xffffffffu, v, 8);
    v += __shfl_xor_sync(0xffffffffu, v, 4);
    v += __shfl_xor_sync(0xffffffffu, v, 2);
    v += __shfl_xor_sync(0xffffffffu, v, 1);
    return v;
}
__device__ __forceinline__ uint32_t f2tf32(float x){
    uint32_t r;
    asm("cvt.rna.tf32.f32 %0, %1;" : "=r"(r) : "f"(x));
    return r;
}
// mma.sync m16n8k8 tf32: D += A(16x8,row) * B(8x8,col)
__device__ __forceinline__ void mma8(float* c, const uint32_t* a, uint32_t b0, uint32_t b1){
    asm volatile("mma.sync.aligned.m16n8k8.row.col.f32.tf32.tf32.f32 "
        "{%0,%1,%2,%3}, {%4,%5,%6,%7}, {%8,%9}, {%0,%1,%2,%3};"
        : "+f"(c[0]), "+f"(c[1]), "+f"(c[2]), "+f"(c[3])
        : "r"(a[0]), "r"(a[1]), "r"(a[2]), "r"(a[3]), "r"(b0), "r"(b1));
}

// ---------------- zero accumulators (graph replays!) ----------------
__global__ void k_zero(){
    int t = threadIdx.x;
    if (t < 5) d_S5[t] = 0.f;
    for (int i = t; i < 6*HDIM; i += blockDim.x) d_T6[i] = 0.f;
}

// ---------------- geometry: n,d per pair + scalar moments ----------------
__global__ void k_geom(const float* __restrict__ p){
    int i = blockIdx.x, b = blockIdx.y;
    int row = b*NSEQ + i;
    int j = threadIdx.x;
    __shared__ float4 pi4s;
    __shared__ float red[8][5];
    if (j == 0) pi4s = reinterpret_cast<const float4*>(p)[row];
    __syncthreads();
    float4 pi = pi4s;
    float4 pj = reinterpret_cast<const float4*>(p)[b*NSEQ + j];
    float d0=pi.x-pj.x, d1=pi.y-pj.y, d2=pi.z-pj.z, d3=pi.w-pj.w;
    float n  = psif(d1*d1 + d2*d2 + d3*d3 - d0*d0);
    float dt = psif(pi.x*pj.x - pi.y*pj.y - pi.z*pj.z - pi.w*pj.w);
    d_G[row*NSEQ + j] = make_float2(n, dt);
    float v0=wsum(n), v1=wsum(dt), v2=wsum(n*n), v3=wsum(dt*dt), v4=wsum(n*dt);
    int lane = j & 31, w = j >> 5;
    if (lane==0){ red[w][0]=v0; red[w][1]=v1; red[w][2]=v2; red[w][3]=v3; red[w][4]=v4; }
    __syncthreads();
    if (j == 0){
        float s0=0,s1=0,s2=0,s3=0,s4=0;
        for (int q=0;q<8;q++){ s0+=red[q][0]; s1+=red[q][1]; s2+=red[q][2]; s3+=red[q][3]; s4+=red[q][4]; }
        d_Rn[row]=s0; d_Rd[row]=s1;
        atomicAdd(&d_S5[0], s0); atomicAdd(&d_S5[1], s1);
        atomicAdd(&d_S5[2], s2); atomicAdd(&d_S5[3], s3); atomicAdd(&d_S5[4], s4);
    }
}

// ---------------- A = h@We1[0:72], B = h@We1[72:144] ----------------
__global__ void k_AB(const float* __restrict__ h, const float* __restrict__ We1){
    __shared__ float Ws[144*HDIM];
    __shared__ float hs[HDIM];
    int row = blockIdx.x;
    int t = threadIdx.x;   // 144 threads
    for (int idx=t; idx<144*HDIM; idx+=144) Ws[idx] = We1[idx];
    if (t < HDIM) hs[t] = h[row*HDIM + t];
    __syncthreads();
    if (t < HDIM){
        float acc = 0.f;
        #pragma unroll 8
        for (int k=0;k<HDIM;k++) acc = fmaf(hs[k], Ws[k*HDIM + t], acc);
        d_A[row*HDIM + t] = acc;
    } else {
        int c = t - HDIM;
        float acc = 0.f;
        #pragma unroll 8
        for (int k=0;k<HDIM;k++) acc = fmaf(hs[k], Ws[(HDIM+k)*HDIM + c], acc);
        d_Bm[row*HDIM + c] = acc;
    }
}

// ---------------- per-channel moments of A,B ----------------
__global__ void k_mom(){
    int c = blockIdx.x, b = blockIdx.y;
    int t = threadIdx.x; // 256
    int r = b*NSEQ + t;
    float a  = d_A [r*HDIM + c];
    float bb = d_Bm[r*HDIM + c];
    float rn = d_Rn[r], rd = d_Rd[r];
    float v[8] = { a, bb, a*a, bb*bb, a*rn, a*rd, bb*rn, bb*rd };
    __shared__ float red[8][8];
    int lane = t & 31, w = t >> 5;
    #pragma unroll
    for (int q=0;q<8;q++){
        float s = wsum(v[q]);
        if (lane==0) red[w][q] = s;
    }
    __syncthreads();
    if (t == 0){
        float s[8];
        #pragma unroll
        for (int q=0;q<8;q++){ s[q]=0.f; for (int ww=0;ww<8;ww++) s[q]+=red[ww][q]; }
        d_SA[b*HDIM + c] = s[0];
        d_SB[b*HDIM + c] = s[1];
        atomicAdd(&d_T6[0*HDIM + c], s[2]);
        atomicAdd(&d_T6[1*HDIM + c], s[3]);
        atomicAdd(&d_T6[2*HDIM + c], s[4]);
        atomicAdd(&d_T6[3*HDIM + c], s[5]);
        atomicAdd(&d_T6[4*HDIM + c], s[6]);
        atomicAdd(&d_T6[5*HDIM + c], s[7]);
    }
}

// ---------------- finalize BN1 scale/shift (exact algebra) ----------------
__global__ void k_bn1(const float* __restrict__ We1, const float* __restrict__ g1,
                      const float* __restrict__ b1){
    int c = threadIdx.x;
    if (c >= HDIM) return;
    float r1 = We1[144*HDIM + c], r2 = We1[145*HDIM + c];
    float SAt=0.f, SBt=0.f, cross=0.f;
    for (int b=0;b<BATCH;b++){
        float sa = d_SA[b*HDIM+c], sb = d_SB[b*HDIM+c];
        SAt += sa; SBt += sb; cross += sa*sb;
    }
    float Sn=d_S5[0], Sd=d_S5[1], Snn=d_S5[2], Sdd=d_S5[3], Snd=d_S5[4];
    float sumx  = 256.f*(SAt + SBt) + r1*Sn + r2*Sd;
    float sumx2 = 256.f*(d_T6[c] + d_T6[HDIM+c])
                + r1*r1*Snn + r2*r2*Sdd
                + 2.f*cross
                + 2.f*r1*(d_T6[2*HDIM+c] + d_T6[4*HDIM+c])
                + 2.f*r2*(d_T6[3*HDIM+c] + d_T6[5*HDIM+c])
                + 2.f*r1*r2*Snd;
    const float P = 1048576.f;
    float mu  = sumx / P;
    float var = sumx2 / P - mu*mu;
    float sc  = g1[c] * rsqrtf(var + 1e-5f);
    d_bn1[c]        = sc;
    d_bn1[HDIM + c] = b1[c] - mu*sc;
}

// ---------------- main pairwise kernel (warp-level tf32 mma.sync) ----------------
// SMEM: Ts[128][TP] tf32 | W2[72*72] tf32 | W1[72*72] tf32 | vectors
#define TS_OFF  0
#define TS_SIZE (128*TP*4)
#define W2_OFF  (TS_OFF + TS_SIZE)
#define W1_OFF  (W2_OFF + HDIM*HDIM*4)
#define VEC_OFF (W1_OFF + HDIM*HDIM*4)

struct KVecs {
    float Avec[HDIM], r1[HDIM], r2[HDIM], scv[HDIM], shv[HDIM];
    float be2v[HDIM], bx1v[HDIM], Wmv[HDIM], Wx2v[HDIM];
    float mg[HDIM];
    float xw[128];
    float aggred[4][4];
    float pis[4];
    float bmv;
};
#define KSMEM_TOTAL (VEC_OFF + (int)sizeof(KVecs))

__device__ __forceinline__ void warp_gemm(const uint32_t* __restrict__ Ts,
                                          const uint32_t* __restrict__ Ws,
                                          int r0, int g, int tig,
                                          float acc[2][9][4]){
    #pragma unroll
    for (int mt=0;mt<2;mt++)
        #pragma unroll
        for (int nt=0;nt<9;nt++)
            #pragma unroll
            for (int c=0;c<4;c++) acc[mt][nt][c]=0.f;
    #pragma unroll
    for (int k=0;k<9;k++){
        int kc = k*8 + tig;
        uint32_t a[2][4];
        #pragma unroll
        for (int mt=0;mt<2;mt++){
            int r = r0 + mt*16 + g;
            a[mt][0] = Ts[ r      *TP + kc    ];
            a[mt][1] = Ts[(r + 8) *TP + kc    ];
            a[mt][2] = Ts[ r      *TP + kc + 4];
            a[mt][3] = Ts[(r + 8) *TP + kc + 4];
        }
        #pragma unroll
        for (int nt=0;nt<9;nt++){
            uint32_t b0 = Ws[ kc     *HDIM + nt*8 + g];
            uint32_t b1 = Ws[(kc+4)  *HDIM + nt*8 + g];
            mma8(acc[0][nt], a[0], b0, b1);
            mma8(acc[1][nt], a[1], b0, b1);
        }
    }
}

__global__ __launch_bounds__(128, 2) void k_main(
    const float* __restrict__ p,   const float* __restrict__ We1,
    const float* __restrict__ We2, const float* __restrict__ be2,
    const float* __restrict__ Wm,  const float* __restrict__ bm,
    const float* __restrict__ Wx1, const float* __restrict__ bx1,
    const float* __restrict__ Wx2, float* __restrict__ out_p)
{
    extern __shared__ unsigned char sm[];
    uint32_t* Ts = reinterpret_cast<uint32_t*>(sm + TS_OFF);
    uint32_t* W2 = reinterpret_cast<uint32_t*>(sm + W2_OFF);
    uint32_t* W1 = reinterpret_cast<uint32_t*>(sm + W1_OFF);
    KVecs*    V  = reinterpret_cast<KVecs*>(sm + VEC_OFF);
    const int i = blockIdx.x, b = blockIdx.y;
    const int row = b*NSEQ + i;
    const int tid  = threadIdx.x;
    const int wid  = tid >> 5;
    const int lane = tid & 31;
    const int g    = lane >> 2;
    const int tig  = lane & 3;
    const int r0   = wid*32;

    // ---- init: weights (cvt to tf32), vectors ----
    for (int t = tid; t < HDIM*HDIM; t += 128){
        W2[t] = f2tf32(We2[t]);
        W1[t] = f2tf32(Wx1[t]);
    }
    if (tid < HDIM){
        V->Avec[tid] = d_A[row*HDIM + tid];
        V->r1[tid]   = We1[144*HDIM + tid];
        V->r2[tid]   = We1[145*HDIM + tid];
        V->scv[tid]  = d_bn1[tid];
        V->shv[tid]  = d_bn1[HDIM + tid];
        V->be2v[tid] = be2[tid];
        V->bx1v[tid] = bx1[tid];
        V->Wmv[tid]  = Wm[tid];
        V->Wx2v[tid] = Wx2[tid];
        V->mg[tid]   = 0.f;
    }
    if (tid < 4)  V->pis[tid] = p[row*4 + tid];
    if (tid == 0) V->bmv = bm[0];
    __syncthreads();

    const float bmv = V->bmv;
    const float4 pis4 = *reinterpret_cast<const float4*>(V->pis);
    float colsum[9][2];
    #pragma unroll
    for (int nt=0;nt<9;nt++){ colsum[nt][0]=0.f; colsum[nt][1]=0.f; }
    float agg0=0.f, agg1=0.f, agg2=0.f, agg3=0.f;

    #pragma unroll 1
    for (int tile = 0; tile < 2; ++tile){
        const int j0 = tile*128;
        // ---- build T row tid : tf32(relu(BN(A_i + B_j + n r1 + d r2)))
        {
            float2 nd = d_G[row*NSEQ + j0 + tid];
            const float4* B4 = reinterpret_cast<const float4*>(d_Bm + (b*NSEQ + j0 + tid)*HDIM);
            #pragma unroll
            for (int q = 0; q < 18; ++q){
                float4 bv = B4[q];
                int c = q*4;
                float v0 = V->Avec[c+0] + bv.x + nd.x*V->r1[c+0] + nd.y*V->r2[c+0];
                float v1 = V->Avec[c+1] + bv.y + nd.x*V->r1[c+1] + nd.y*V->r2[c+1];
                float v2 = V->Avec[c+2] + bv.z + nd.x*V->r1[c+2] + nd.y*V->r2[c+2];
                float v3 = V->Avec[c+3] + bv.w + nd.x*V->r1[c+3] + nd.y*V->r2[c+3];
                uint4 o;
                o.x = f2tf32(fmaxf(fmaf(v0, V->scv[c+0], V->shv[c+0]), 0.f));
                o.y = f2tf32(fmaxf(fmaf(v1, V->scv[c+1], V->shv[c+1]), 0.f));
                o.z = f2tf32(fmaxf(fmaf(v2, V->scv[c+2], V->shv[c+2]), 0.f));
                o.w = f2tf32(fmaxf(fmaf(v3, V->scv[c+3], V->shv[c+3]), 0.f));
                *reinterpret_cast<uint4*>(&Ts[tid*TP + c]) = o;
            }
        }
        __syncwarp();

        // ---- GEMM1: acc = T @ We2 (warp rows r0..r0+31)
        float acc[2][9][4];
        warp_gemm(Ts, W2, r0, g, tig, acc);
        __syncwarp();

        // ---- epi1: m = relu(acc + be2); dot m.Wm; sigmoid; wm = m*w
        float dotv[2][2] = {{0.f,0.f},{0.f,0.f}};
        #pragma unroll
        for (int mt=0;mt<2;mt++)
            #pragma unroll
            for (int nt=0;nt<9;nt++)
                #pragma unroll
                for (int cc=0;cc<4;cc++){
                    int col = nt*8 + 2*tig + (cc&1);
                    float m = fmaxf(acc[mt][nt][cc] + V->be2v[col], 0.f);
                    acc[mt][nt][cc] = m;
                    dotv[mt][cc>>1] += m * V->Wmv[col];
                }
        float wgt[2][2];
        #pragma unroll
        for (int mt=0;mt<2;mt++)
            #pragma unroll
            for (int hh=0;hh<2;hh++){
                float v = dotv[mt][hh];
                v += __shfl_xor_sync(0xffffffffu, v, 1);
                v += __shfl_xor_sync(0xffffffffu, v, 2);
                wgt[mt][hh] = 1.f / (1.f + expf(-(v + bmv)));
            }
        // wm: scale, accumulate column sums, store tf32 back to Ts
        #pragma unroll
        for (int mt=0;mt<2;mt++){
            int rlo = r0 + mt*16 + g;
            #pragma unroll
            for (int nt=0;nt<9;nt++){
                float l0 = acc[mt][nt][0]*wgt[mt][0];
                float l1 = acc[mt][nt][1]*wgt[mt][0];
                float h0 = acc[mt][nt][2]*wgt[mt][1];
                float h1 = acc[mt][nt][3]*wgt[mt][1];
                colsum[nt][0] += l0 + h0;
                colsum[nt][1] += l1 + h1;
                int cb = nt*8 + 2*tig;
                uint2 ulo; ulo.x = f2tf32(l0); ulo.y = f2tf32(l1);
                uint2 uhi; uhi.x = f2tf32(h0); uhi.y = f2tf32(h1);
                *reinterpret_cast<uint2*>(&Ts[ rlo    *TP + cb]) = ulo;
                *reinterpret_cast<uint2*>(&Ts[(rlo+8) *TP + cb]) = uhi;
            }
        }
        __syncwarp();

        // ---- GEMM2: acc = wm @ Wx1
        warp_gemm(Ts, W1, r0, g, tig, acc);

        // ---- epi2: u = relu(acc + bx1); xw = u . Wx2 per row
        float px[2][2] = {{0.f,0.f},{0.f,0.f}};
        #pragma unroll
        for (int mt=0;mt<2;mt++)
            #pragma unroll
            for (int nt=0;nt<9;nt++)
                #pragma unroll
                for (int cc=0;cc<4;cc++){
                    int col = nt*8 + 2*tig + (cc&1);
                    float u = fmaxf(acc[mt][nt][cc] + V->bx1v[col], 0.f);
                    px[mt][cc>>1] += u * V->Wx2v[col];
                }
        #pragma unroll
        for (int mt=0;mt<2;mt++)
            #pragma unroll
            for (int hh=0;hh<2;hh++){
                float v = px[mt][hh];
                v += __shfl_xor_sync(0xffffffffu, v, 1);
                v += __shfl_xor_sync(0xffffffffu, v, 2);
                if (tig == 0) V->xw[r0 + mt*16 + hh*8 + g] = v;
            }
        __syncwarp();

        // ---- aggs: row j0+tid handled by thread tid (same warp as writer)
        {
            float x = V->xw[tid];
            float4 pj = reinterpret_cast<const float4*>(p)[b*NSEQ + j0 + tid];
            agg0 += fminf(fmaxf((pis4.x - pj.x)*x, -100.f), 100.f);
            agg1 += fminf(fmaxf((pis4.y - pj.y)*x, -100.f), 100.f);
            agg2 += fminf(fmaxf((pis4.z - pj.z)*x, -100.f), 100.f);
            agg3 += fminf(fmaxf((pis4.w - pj.w)*x, -100.f), 100.f);
        }
        __syncwarp();   // Ts rows free for next tile build
    }

    // ---- magg: reduce colsum over g-lanes, add into V->mg
    #pragma unroll
    for (int nt=0;nt<9;nt++)
        #pragma unroll
        for (int d=0;d<2;d++){
            float v = colsum[nt][d];
            v += __shfl_xor_sync(0xffffffffu, v, 4);
            v += __shfl_xor_sync(0xffffffffu, v, 8);
            v += __shfl_xor_sync(0xffffffffu, v, 16);
            if (g == 0) atomicAdd(&V->mg[nt*8 + 2*tig + d], v);
        }
    // ---- agg reduce across warps
    {
        float s0=wsum(agg0), s1=wsum(agg1), s2=wsum(agg2), s3=wsum(agg3);
        if (lane==0){ V->aggred[wid][0]=s0; V->aggred[wid][1]=s1; V->aggred[wid][2]=s2; V->aggred[wid][3]=s3; }
    }
    __syncthreads();
    if (tid < HDIM) d_magg[row*HDIM + tid] = V->mg[tid];
    if (tid < 4){
        float s = V->aggred[0][tid]+V->aggred[1][tid]+V->aggred[2][tid]+V->aggred[3][tid];
        out_p[row*4 + tid] = V->pis[tid] + (s * (1.f/256.f)) * 0.001f;
    }
}

// ---------------- h-path: y0 = [h,magg,s] @ Wh1 + bh1 ----------------
__global__ void k_y0(const float* __restrict__ h, const float* __restrict__ s,
                     const float* __restrict__ Wh1, const float* __restrict__ bh1){
    __shared__ float hin[2*HDIM + SDIM];
    int row = blockIdx.x;
    int t = threadIdx.x; // 160
    if (t < HDIM)               hin[t] = h[row*HDIM + t];
    else if (t < 2*HDIM)        hin[t] = d_magg[row*HDIM + (t - HDIM)];
    else if (t < 2*HDIM + SDIM) hin[t] = s[row*SDIM + (t - 2*HDIM)];
    __syncthreads();
    if (t < HDIM){
        float acc = bh1[t];
        #pragma unroll 8
        for (int k=0;k<2*HDIM+SDIM;k++) acc = fmaf(hin[k], Wh1[k*HDIM + t], acc);
        d_y0[row*HDIM + t] = acc;
    }
}

__global__ void k_bn2(const float* __restrict__ gh, const float* __restrict__ bh){
    int c = blockIdx.x;
    int t = threadIdx.x; // 256
    float sum=0.f, sq=0.f;
    for (int r=t; r<ROWS; r+=256){
        float v = d_y0[r*HDIM + c];
        sum += v; sq += v*v;
    }
    __shared__ float red[8][2];
    float s0 = wsum(sum), s1 = wsum(sq);
    int lane=t&31, w=t>>5;
    if (lane==0){ red[w][0]=s0; red[w][1]=s1; }
    __syncthreads();
    if (t==0){
        float a=0.f,bb=0.f;
        for (int q=0;q<8;q++){ a+=red[q][0]; bb+=red[q][1]; }
        float mu  = a / 4096.f;
        float var = bb / 4096.f - mu*mu;
        float sc  = gh[c] * rsqrtf(var + 1e-5f);
        d_bn2[c]        = sc;
        d_bn2[HDIM + c] = bh[c] - mu*sc;
    }
}

__global__ void k_hout(const float* __restrict__ h, const float* __restrict__ Wh2,
                       const float* __restrict__ bh2, float* __restrict__ out_h){
    __shared__ float yr[HDIM];
    __shared__ float W[HDIM*HDIM];
    int row = blockIdx.x;
    int t = threadIdx.x; // 128
    if (t < HDIM) yr[t] = fmaxf(fmaf(d_y0[row*HDIM+t], d_bn2[t], d_bn2[HDIM+t]), 0.f);
    for (int idx=t; idx<HDIM*HDIM; idx+=128) W[idx] = Wh2[idx];
    __syncthreads();
    if (t < HDIM){
        float acc = bh2[t];
        #pragma unroll 8
        for (int k=0;k<HDIM;k++) acc = fmaf(yr[k], W[k*HDIM + t], acc);
        out_h[row*HDIM + t] = h[row*HDIM + t] + acc;
    }
}

// ---------------- launch ----------------
extern "C" void kernel_launch(void* const* d_in, const int* in_sizes, int n_in,
                              void* d_out, int out_size){
    const float* h   = (const float*)d_in[0];
    const float* p   = (const float*)d_in[1];
    const float* s   = (const float*)d_in[2];
    const float* We1 = (const float*)d_in[3];
    const float* g1  = (const float*)d_in[4];
    const float* b1  = (const float*)d_in[5];
    const float* We2 = (const float*)d_in[6];
    const float* be2 = (const float*)d_in[7];
    const float* Wm  = (const float*)d_in[8];
    const float* bm  = (const float*)d_in[9];
    const float* Wx1 = (const float*)d_in[10];
    const float* bx1 = (const float*)d_in[11];
    const float* Wx2 = (const float*)d_in[12];
    const float* Wh1 = (const float*)d_in[13];
    const float* bh1 = (const float*)d_in[14];
    const float* gh  = (const float*)d_in[15];
    const float* bh  = (const float*)d_in[16];
    const float* Wh2 = (const float*)d_in[17];
    const float* bh2 = (const float*)d_in[18];
    float* out   = (float*)d_out;
    float* out_h = out;                 // (B,N,H) first
    float* out_p = out + ROWS*HDIM;     // then (B,N,4)

    cudaFuncSetAttribute(k_main, cudaFuncAttributeMaxDynamicSharedMemorySize, KSMEM_TOTAL);

    k_zero<<<1, 512>>>();
    k_geom<<<dim3(NSEQ, BATCH), NSEQ>>>(p);
    k_AB  <<<ROWS, 144>>>(h, We1);
    k_mom <<<dim3(HDIM, BATCH), 256>>>();
    k_bn1 <<<1, HDIM>>>(We1, g1, b1);
    k_main<<<dim3(NSEQ, BATCH), 128, KSMEM_TOTAL>>>(p, We1, We2, be2, Wm, bm, Wx1, bx1, Wx2, out_p);
    k_y0  <<<ROWS, 160>>>(h, s, Wh1, bh1);
    k_bn2 <<<HDIM, 256>>>(gh, bh);
    k_hout<<<ROWS, 128>>>(h, Wh2, bh2, out_h);
}

// round 8
// speedup vs baseline: 2.3215x; 1.1205x over previous
#include <cuda_runtime.h>
#include <cuda_fp16.h>
#include <math.h>
#include <stdint.h>

#define HDIM 72
#define NSEQ 256
#define BATCH 16
#define ROWS 4096          // BATCH*NSEQ
#define PAIRS 1048576      // ROWS*NSEQ
#define SDIM 13
#define HP 88              // half-pitch: bank=(12g+tig)%32 -> conflict-free frags

// ---------------- device scratch (static, no runtime alloc) ----------------
__device__ float  d_A [ROWS*HDIM];
__device__ float  d_Bm[ROWS*HDIM];
__device__ float2 d_G [PAIRS];
__device__ float  d_Rn[ROWS];
__device__ float  d_Rd[ROWS];
__device__ float  d_S5[5];          // Sn, Sd, Snn, Sdd, Snd
__device__ float  d_SA[BATCH*HDIM];
__device__ float  d_SB[BATCH*HDIM];
__device__ float  d_T6[6*HDIM];     // TAA,TBB,TAn,TAd,TBn,TBd
__device__ float  d_bn1[2*HDIM];    // scale, shift
__device__ float  d_magg[ROWS*HDIM];
__device__ float  d_y0 [ROWS*HDIM];
__device__ float  d_bn2[2*HDIM];

__device__ __forceinline__ float psif(float x){
    return copysignf(log1pf(fabsf(x)), x);
}
__device__ __forceinline__ float wsum(float v){
    v += __shfl_xor_sync(0xffffffffu, v, 16);
    v += __shfl_xor_sync(0xffffffffu, v, 8);
    v += __shfl_xor_sync(0xffffffffu, v, 4);
    v += __shfl_xor_sync(0xffffffffu, v, 2);
    v += __shfl_xor_sync(0xffffffffu, v, 1);
    return v;
}
// mma.sync m16n8k16 fp16 in, fp32 accum
__device__ __forceinline__ void mma16(float* c, uint32_t a0, uint32_t a1, uint32_t a2,
                                      uint32_t a3, uint32_t b0, uint32_t b1){
    asm volatile("mma.sync.aligned.m16n8k16.row.col.f32.f16.f16.f32 "
        "{%0,%1,%2,%3}, {%4,%5,%6,%7}, {%8,%9}, {%0,%1,%2,%3};"
        : "+f"(c[0]), "+f"(c[1]), "+f"(c[2]), "+f"(c[3])
        : "r"(a0), "r"(a1), "r"(a2), "r"(a3), "r"(b0), "r"(b1));
}

// ---------------- zero accumulators (graph replays!) ----------------
__global__ void k_zero(){
    int t = threadIdx.x;
    if (t < 5) d_S5[t] = 0.f;
    for (int i = t; i < 6*HDIM; i += blockDim.x) d_T6[i] = 0.f;
}

// ---------------- geometry: n,d per pair + scalar moments ----------------
__global__ void k_geom(const float* __restrict__ p){
    int i = blockIdx.x, b = blockIdx.y;
    int row = b*NSEQ + i;
    int j = threadIdx.x;
    __shared__ float4 pi4s;
    __shared__ float red[8][5];
    if (j == 0) pi4s = reinterpret_cast<const float4*>(p)[row];
    __syncthreads();
    float4 pi = pi4s;
    float4 pj = reinterpret_cast<const float4*>(p)[b*NSEQ + j];
    float d0=pi.x-pj.x, d1=pi.y-pj.y, d2=pi.z-pj.z, d3=pi.w-pj.w;
    float n  = psif(d1*d1 + d2*d2 + d3*d3 - d0*d0);
    float dt = psif(pi.x*pj.x - pi.y*pj.y - pi.z*pj.z - pi.w*pj.w);
    d_G[row*NSEQ + j] = make_float2(n, dt);
    float v0=wsum(n), v1=wsum(dt), v2=wsum(n*n), v3=wsum(dt*dt), v4=wsum(n*dt);
    int lane = j & 31, w = j >> 5;
    if (lane==0){ red[w][0]=v0; red[w][1]=v1; red[w][2]=v2; red[w][3]=v3; red[w][4]=v4; }
    __syncthreads();
    if (j == 0){
        float s0=0,s1=0,s2=0,s3=0,s4=0;
        for (int q=0;q<8;q++){ s0+=red[q][0]; s1+=red[q][1]; s2+=red[q][2]; s3+=red[q][3]; s4+=red[q][4]; }
        d_Rn[row]=s0; d_Rd[row]=s1;
        atomicAdd(&d_S5[0], s0); atomicAdd(&d_S5[1], s1);
        atomicAdd(&d_S5[2], s2); atomicAdd(&d_S5[3], s3); atomicAdd(&d_S5[4], s4);
    }
}

// ---------------- A = h@We1[0:72], B = h@We1[72:144] ----------------
__global__ void k_AB(const float* __restrict__ h, const float* __restrict__ We1){
    __shared__ float Ws[144*HDIM];
    __shared__ float hs[HDIM];
    int row = blockIdx.x;
    int t = threadIdx.x;   // 144 threads
    for (int idx=t; idx<144*HDIM; idx+=144) Ws[idx] = We1[idx];
    if (t < HDIM) hs[t] = h[row*HDIM + t];
    __syncthreads();
    if (t < HDIM){
        float acc = 0.f;
        #pragma unroll 8
        for (int k=0;k<HDIM;k++) acc = fmaf(hs[k], Ws[k*HDIM + t], acc);
        d_A[row*HDIM + t] = acc;
    } else {
        int c = t - HDIM;
        float acc = 0.f;
        #pragma unroll 8
        for (int k=0;k<HDIM;k++) acc = fmaf(hs[k], Ws[(HDIM+k)*HDIM + c], acc);
        d_Bm[row*HDIM + c] = acc;
    }
}

// ---------------- per-channel moments of A,B ----------------
__global__ void k_mom(){
    int c = blockIdx.x, b = blockIdx.y;
    int t = threadIdx.x; // 256
    int r = b*NSEQ + t;
    float a  = d_A [r*HDIM + c];
    float bb = d_Bm[r*HDIM + c];
    float rn = d_Rn[r], rd = d_Rd[r];
    float v[8] = { a, bb, a*a, bb*bb, a*rn, a*rd, bb*rn, bb*rd };
    __shared__ float red[8][8];
    int lane = t & 31, w = t >> 5;
    #pragma unroll
    for (int q=0;q<8;q++){
        float s = wsum(v[q]);
        if (lane==0) red[w][q] = s;
    }
    __syncthreads();
    if (t == 0){
        float s[8];
        #pragma unroll
        for (int q=0;q<8;q++){ s[q]=0.f; for (int ww=0;ww<8;ww++) s[q]+=red[ww][q]; }
        d_SA[b*HDIM + c] = s[0];
        d_SB[b*HDIM + c] = s[1];
        atomicAdd(&d_T6[0*HDIM + c], s[2]);
        atomicAdd(&d_T6[1*HDIM + c], s[3]);
        atomicAdd(&d_T6[2*HDIM + c], s[4]);
        atomicAdd(&d_T6[3*HDIM + c], s[5]);
        atomicAdd(&d_T6[4*HDIM + c], s[6]);
        atomicAdd(&d_T6[5*HDIM + c], s[7]);
    }
}

// ---------------- finalize BN1 scale/shift (exact algebra) ----------------
__global__ void k_bn1(const float* __restrict__ We1, const float* __restrict__ g1,
                      const float* __restrict__ b1){
    int c = threadIdx.x;
    if (c >= HDIM) return;
    float r1 = We1[144*HDIM + c], r2 = We1[145*HDIM + c];
    float SAt=0.f, SBt=0.f, cross=0.f;
    for (int b=0;b<BATCH;b++){
        float sa = d_SA[b*HDIM+c], sb = d_SB[b*HDIM+c];
        SAt += sa; SBt += sb; cross += sa*sb;
    }
    float Sn=d_S5[0], Sd=d_S5[1], Snn=d_S5[2], Sdd=d_S5[3], Snd=d_S5[4];
    float sumx  = 256.f*(SAt + SBt) + r1*Sn + r2*Sd;
    float sumx2 = 256.f*(d_T6[c] + d_T6[HDIM+c])
                + r1*r1*Snn + r2*r2*Sdd
                + 2.f*cross
                + 2.f*r1*(d_T6[2*HDIM+c] + d_T6[4*HDIM+c])
                + 2.f*r2*(d_T6[3*HDIM+c] + d_T6[5*HDIM+c])
                + 2.f*r1*r2*Snd;
    const float P = 1048576.f;
    float mu  = sumx / P;
    float var = sumx2 / P - mu*mu;
    float sc  = g1[c] * rsqrtf(var + 1e-5f);
    d_bn1[c]        = sc;
    d_bn1[HDIM + c] = b1[c] - mu*sc;
}

// ---------------- main pairwise kernel (fp16 m16n8k16 mma.sync) ----------------
// SMEM (halves): Ts[128][HP] | W2c[72][HP] (col-major [n][k]) | W1c[72][HP] | vectors
#define TS_OFF  0
#define TS_BYTES (128*HP*2)
#define W2_OFF  (TS_OFF + TS_BYTES)
#define W1_OFF  (W2_OFF + HDIM*HP*2)
#define VEC_OFF (W1_OFF + HDIM*HP*2)

struct KVecs {
    float Avec[HDIM], r1[HDIM], r2[HDIM], scv[HDIM], shv[HDIM];
    float be2v[HDIM], bx1v[HDIM], Wmv[HDIM], Wx2v[HDIM];
    float mg[HDIM];
    float aggred[8][4];
    float pis[4];
    float bmv;
};
#define KSMEM_TOTAL (VEC_OFF + (int)sizeof(KVecs))

__global__ __launch_bounds__(256, 2) void k_main(
    const float* __restrict__ p,   const float* __restrict__ We1,
    const float* __restrict__ We2, const float* __restrict__ be2,
    const float* __restrict__ Wm,  const float* __restrict__ bm,
    const float* __restrict__ Wx1, const float* __restrict__ bx1,
    const float* __restrict__ Wx2, float* __restrict__ out_p)
{
    extern __shared__ unsigned char sm[];
    __half* Ts  = reinterpret_cast<__half*>(sm + TS_OFF);
    __half* W2c = reinterpret_cast<__half*>(sm + W2_OFF);
    __half* W1c = reinterpret_cast<__half*>(sm + W1_OFF);
    KVecs*  V   = reinterpret_cast<KVecs*>(sm + VEC_OFF);
    const int i = blockIdx.x, b = blockIdx.y;
    const int row = b*NSEQ + i;
    const int tid  = threadIdx.x;
    const int wid  = tid >> 5;       // 0..7
    const int lane = tid & 31;
    const int g    = lane >> 2;
    const int tig  = lane & 3;
    const int r0   = wid*16;         // warp's 16 rows

    // ---- init: transpose weights to [n][k] fp16 with K padded to 80 ----
    for (int t = tid; t < HDIM*80; t += 256){
        int k = t / HDIM, n = t - k*HDIM;   // k 0..79, n 0..71 (loads coalesced in n)
        if (k < HDIM){
            W2c[n*HP + k] = __float2half_rn(We2[k*HDIM + n]);
            W1c[n*HP + k] = __float2half_rn(Wx1[k*HDIM + n]);
        } else {
            W2c[n*HP + k] = __float2half_rn(0.f);
            W1c[n*HP + k] = __float2half_rn(0.f);
        }
    }
    if (tid < 128){   // zero Ts pad cols 72..79 (never touched again)
        uint4 z = make_uint4(0u,0u,0u,0u);
        *reinterpret_cast<uint4*>(Ts + tid*HP + 72) = z;
    }
    if (tid < HDIM){
        V->Avec[tid] = d_A[row*HDIM + tid];
        V->r1[tid]   = We1[144*HDIM + tid];
        V->r2[tid]   = We1[145*HDIM + tid];
        V->scv[tid]  = d_bn1[tid];
        V->shv[tid]  = d_bn1[HDIM + tid];
        V->be2v[tid] = be2[tid];
        V->bx1v[tid] = bx1[tid];
        V->Wmv[tid]  = Wm[tid];
        V->Wx2v[tid] = Wx2[tid];
        V->mg[tid]   = 0.f;
    }
    if (tid < 4)  V->pis[tid] = p[row*4 + tid];
    if (tid == 0) V->bmv = bm[0];
    __syncthreads();

    const float bmv = V->bmv;
    const float4 pis4 = *reinterpret_cast<const float4*>(V->pis);
    float colsum[9][2];
    #pragma unroll
    for (int nt=0;nt<9;nt++){ colsum[nt][0]=0.f; colsum[nt][1]=0.f; }
    float agg0=0.f, agg1=0.f, agg2=0.f, agg3=0.f;

    const int brow = tid >> 1;            // row this thread builds (0..127)
    const int bc0  = (tid & 1) * 36;      // col offset within row

    #pragma unroll 1
    for (int tile = 0; tile < 2; ++tile){
        const int j0 = tile*128;
        // ---- build: warp w's lanes build exactly rows 16w..16w+15 (warp-local)
        {
            float2 nd = d_G[row*NSEQ + j0 + brow];
            const float4* B4 = reinterpret_cast<const float4*>(d_Bm + (b*NSEQ + j0 + brow)*HDIM + bc0);
            #pragma unroll
            for (int q = 0; q < 9; ++q){
                float4 bv = B4[q];
                int c = bc0 + q*4;
                float v0 = V->Avec[c+0] + bv.x + nd.x*V->r1[c+0] + nd.y*V->r2[c+0];
                float v1 = V->Avec[c+1] + bv.y + nd.x*V->r1[c+1] + nd.y*V->r2[c+1];
                float v2 = V->Avec[c+2] + bv.z + nd.x*V->r1[c+2] + nd.y*V->r2[c+2];
                float v3 = V->Avec[c+3] + bv.w + nd.x*V->r1[c+3] + nd.y*V->r2[c+3];
                v0 = fmaxf(fmaf(v0, V->scv[c+0], V->shv[c+0]), 0.f);
                v1 = fmaxf(fmaf(v1, V->scv[c+1], V->shv[c+1]), 0.f);
                v2 = fmaxf(fmaf(v2, V->scv[c+2], V->shv[c+2]), 0.f);
                v3 = fmaxf(fmaf(v3, V->scv[c+3], V->shv[c+3]), 0.f);
                __half2 hlo = __floats2half2_rn(v0, v1);
                __half2 hhi = __floats2half2_rn(v2, v3);
                uint2 u; u.x = *reinterpret_cast<uint32_t*>(&hlo); u.y = *reinterpret_cast<uint32_t*>(&hhi);
                *reinterpret_cast<uint2*>(Ts + brow*HP + c) = u;
            }
        }
        __syncwarp();

        // ---- GEMM1: acc = T @ We2 (rows r0..r0+15), K=80 in 5 k16-steps
        float acc[9][4];
        #pragma unroll
        for (int nt=0;nt<9;nt++){ acc[nt][0]=0.f; acc[nt][1]=0.f; acc[nt][2]=0.f; acc[nt][3]=0.f; }
        #pragma unroll
        for (int kk=0;kk<5;kk++){
            int kb = kk*16 + 2*tig;
            uint32_t a0 = *reinterpret_cast<const uint32_t*>(Ts + (r0+g  )*HP + kb);
            uint32_t a1 = *reinterpret_cast<const uint32_t*>(Ts + (r0+g+8)*HP + kb);
            uint32_t a2 = *reinterpret_cast<const uint32_t*>(Ts + (r0+g  )*HP + kb + 8);
            uint32_t a3 = *reinterpret_cast<const uint32_t*>(Ts + (r0+g+8)*HP + kb + 8);
            #pragma unroll
            for (int nt=0;nt<9;nt++){
                uint32_t b0 = *reinterpret_cast<const uint32_t*>(W2c + (nt*8+g)*HP + kb);
                uint32_t b1 = *reinterpret_cast<const uint32_t*>(W2c + (nt*8+g)*HP + kb + 8);
                mma16(acc[nt], a0, a1, a2, a3, b0, b1);
            }
        }
        __syncwarp();

        // ---- epi1: m = relu(acc+be2); w = sigmoid(m.Wm+bm); wm = m*w -> Ts
        float dotv[2] = {0.f, 0.f};
        #pragma unroll
        for (int nt=0;nt<9;nt++)
            #pragma unroll
            for (int cc=0;cc<4;cc++){
                int col = nt*8 + 2*tig + (cc&1);
                float m = fmaxf(acc[nt][cc] + V->be2v[col], 0.f);
                acc[nt][cc] = m;
                dotv[cc>>1] += m * V->Wmv[col];
            }
        float wgt[2];
        #pragma unroll
        for (int hh=0;hh<2;hh++){
            float v = dotv[hh];
            v += __shfl_xor_sync(0xffffffffu, v, 1);
            v += __shfl_xor_sync(0xffffffffu, v, 2);
            wgt[hh] = 1.f / (1.f + expf(-(v + bmv)));
        }
        #pragma unroll
        for (int nt=0;nt<9;nt++){
            float l0 = acc[nt][0]*wgt[0];
            float l1 = acc[nt][1]*wgt[0];
            float h0 = acc[nt][2]*wgt[1];
            float h1 = acc[nt][3]*wgt[1];
            colsum[nt][0] += l0 + h0;
            colsum[nt][1] += l1 + h1;
            int cb = nt*8 + 2*tig;
            __half2 lo = __floats2half2_rn(l0, l1);
            __half2 hi = __floats2half2_rn(h0, h1);
            *reinterpret_cast<uint32_t*>(Ts + (r0+g  )*HP + cb) = *reinterpret_cast<uint32_t*>(&lo);
            *reinterpret_cast<uint32_t*>(Ts + (r0+g+8)*HP + cb) = *reinterpret_cast<uint32_t*>(&hi);
        }
        __syncwarp();

        // ---- GEMM2: acc = wm @ Wx1
        #pragma unroll
        for (int nt=0;nt<9;nt++){ acc[nt][0]=0.f; acc[nt][1]=0.f; acc[nt][2]=0.f; acc[nt][3]=0.f; }
        #pragma unroll
        for (int kk=0;kk<5;kk++){
            int kb = kk*16 + 2*tig;
            uint32_t a0 = *reinterpret_cast<const uint32_t*>(Ts + (r0+g  )*HP + kb);
            uint32_t a1 = *reinterpret_cast<const uint32_t*>(Ts + (r0+g+8)*HP + kb);
            uint32_t a2 = *reinterpret_cast<const uint32_t*>(Ts + (r0+g  )*HP + kb + 8);
            uint32_t a3 = *reinterpret_cast<const uint32_t*>(Ts + (r0+g+8)*HP + kb + 8);
            #pragma unroll
            for (int nt=0;nt<9;nt++){
                uint32_t b0 = *reinterpret_cast<const uint32_t*>(W1c + (nt*8+g)*HP + kb);
                uint32_t b1 = *reinterpret_cast<const uint32_t*>(W1c + (nt*8+g)*HP + kb + 8);
                mma16(acc[nt], a0, a1, a2, a3, b0, b1);
            }
        }

        // ---- epi2: u = relu(acc+bx1); xw = u.Wx2; tig0 lane does its rows' aggs
        float px[2] = {0.f, 0.f};
        #pragma unroll
        for (int nt=0;nt<9;nt++)
            #pragma unroll
            for (int cc=0;cc<4;cc++){
                int col = nt*8 + 2*tig + (cc&1);
                float u = fmaxf(acc[nt][cc] + V->bx1v[col], 0.f);
                px[cc>>1] += u * V->Wx2v[col];
            }
        #pragma unroll
        for (int hh=0;hh<2;hh++){
            float v = px[hh];
            v += __shfl_xor_sync(0xffffffffu, v, 1);
            v += __shfl_xor_sync(0xffffffffu, v, 2);
            if (tig == 0){
                int j = j0 + r0 + hh*8 + g;
                float4 pj = reinterpret_cast<const float4*>(p)[b*NSEQ + j];
                agg0 += fminf(fmaxf((pis4.x - pj.x)*v, -100.f), 100.f);
                agg1 += fminf(fmaxf((pis4.y - pj.y)*v, -100.f), 100.f);
                agg2 += fminf(fmaxf((pis4.z - pj.z)*v, -100.f), 100.f);
                agg3 += fminf(fmaxf((pis4.w - pj.w)*v, -100.f), 100.f);
            }
        }
        __syncwarp();   // Ts rows free for next tile build
    }

    // ---- magg: reduce colsum over g-lanes, atomic into V->mg
    #pragma unroll
    for (int nt=0;nt<9;nt++)
        #pragma unroll
        for (int d=0;d<2;d++){
            float v = colsum[nt][d];
            v += __shfl_xor_sync(0xffffffffu, v, 4);
            v += __shfl_xor_sync(0xffffffffu, v, 8);
            v += __shfl_xor_sync(0xffffffffu, v, 16);
            if (g == 0) atomicAdd(&V->mg[nt*8 + 2*tig + d], v);
        }
    // ---- agg reduce across warps
    {
        float s0=wsum(agg0), s1=wsum(agg1), s2=wsum(agg2), s3=wsum(agg3);
        if (lane==0){ V->aggred[wid][0]=s0; V->aggred[wid][1]=s1; V->aggred[wid][2]=s2; V->aggred[wid][3]=s3; }
    }
    __syncthreads();
    if (tid < HDIM) d_magg[row*HDIM + tid] = V->mg[tid];
    if (tid < 4){
        float s = 0.f;
        #pragma unroll
        for (int w=0;w<8;w++) s += V->aggred[w][tid];
        out_p[row*4 + tid] = V->pis[tid] + (s * (1.f/256.f)) * 0.001f;
    }
}

// ---------------- h-path: y0 = [h,magg,s] @ Wh1 + bh1 ----------------
__global__ void k_y0(const float* __restrict__ h, const float* __restrict__ s,
                     const float* __restrict__ Wh1, const float* __restrict__ bh1){
    __shared__ float hin[2*HDIM + SDIM];
    int row = blockIdx.x;
    int t = threadIdx.x; // 160
    if (t < HDIM)               hin[t] = h[row*HDIM + t];
    else if (t < 2*HDIM)        hin[t] = d_magg[row*HDIM + (t - HDIM)];
    else if (t < 2*HDIM + SDIM) hin[t] = s[row*SDIM + (t - 2*HDIM)];
    __syncthreads();
    if (t < HDIM){
        float acc = bh1[t];
        #pragma unroll 8
        for (int k=0;k<2*HDIM+SDIM;k++) acc = fmaf(hin[k], Wh1[k*HDIM + t], acc);
        d_y0[row*HDIM + t] = acc;
    }
}

__global__ void k_bn2(const float* __restrict__ gh, const float* __restrict__ bh){
    int c = blockIdx.x;
    int t = threadIdx.x; // 256
    float sum=0.f, sq=0.f;
    for (int r=t; r<ROWS; r+=256){
        float v = d_y0[r*HDIM + c];
        sum += v; sq += v*v;
    }
    __shared__ float red[8][2];
    float s0 = wsum(sum), s1 = wsum(sq);
    int lane=t&31, w=t>>5;
    if (lane==0){ red[w][0]=s0; red[w][1]=s1; }
    __syncthreads();
    if (t==0){
        float a=0.f,bb=0.f;
        for (int q=0;q<8;q++){ a+=red[q][0]; bb+=red[q][1]; }
        float mu  = a / 4096.f;
        float var = bb / 4096.f - mu*mu;
        float sc  = gh[c] * rsqrtf(var + 1e-5f);
        d_bn2[c]        = sc;
        d_bn2[HDIM + c] = bh[c] - mu*sc;
    }
}

__global__ void k_hout(const float* __restrict__ h, const float* __restrict__ Wh2,
                       const float* __restrict__ bh2, float* __restrict__ out_h){
    __shared__ float yr[HDIM];
    __shared__ float W[HDIM*HDIM];
    int row = blockIdx.x;
    int t = threadIdx.x; // 128
    if (t < HDIM) yr[t] = fmaxf(fmaf(d_y0[row*HDIM+t], d_bn2[t], d_bn2[HDIM+t]), 0.f);
    for (int idx=t; idx<HDIM*HDIM; idx+=128) W[idx] = Wh2[idx];
    __syncthreads();
    if (t < HDIM){
        float acc = bh2[t];
        #pragma unroll 8
        for (int k=0;k<HDIM;k++) acc = fmaf(yr[k], W[k*HDIM + t], acc);
        out_h[row*HDIM + t] = h[row*HDIM + t] + acc;
    }
}

// ---------------- launch ----------------
extern "C" void kernel_launch(void* const* d_in, const int* in_sizes, int n_in,
                              void* d_out, int out_size){
    const float* h   = (const float*)d_in[0];
    const float* p   = (const float*)d_in[1];
    const float* s   = (const float*)d_in[2];
    const float* We1 = (const float*)d_in[3];
    const float* g1  = (const float*)d_in[4];
    const float* b1  = (const float*)d_in[5];
    const float* We2 = (const float*)d_in[6];
    const float* be2 = (const float*)d_in[7];
    const float* Wm  = (const float*)d_in[8];
    const float* bm  = (const float*)d_in[9];
    const float* Wx1 = (const float*)d_in[10];
    const float* bx1 = (const float*)d_in[11];
    const float* Wx2 = (const float*)d_in[12];
    const float* Wh1 = (const float*)d_in[13];
    const float* bh1 = (const float*)d_in[14];
    const float* gh  = (const float*)d_in[15];
    const float* bh  = (const float*)d_in[16];
    const float* Wh2 = (const float*)d_in[17];
    const float* bh2 = (const float*)d_in[18];
    float* out   = (float*)d_out;
    float* out_h = out;                 // (B,N,H) first
    float* out_p = out + ROWS*HDIM;     // then (B,N,4)

    cudaFuncSetAttribute(k_main, cudaFuncAttributeMaxDynamicSharedMemorySize, KSMEM_TOTAL);

    k_zero<<<1, 512>>>();
    k_geom<<<dim3(NSEQ, BATCH), NSEQ>>>(p);
    k_AB  <<<ROWS, 144>>>(h, We1);
    k_mom <<<dim3(HDIM, BATCH), 256>>>();
    k_bn1 <<<1, HDIM>>>(We1, g1, b1);
    k_main<<<dim3(NSEQ, BATCH), 256, KSMEM_TOTAL>>>(p, We1, We2, be2, Wm, bm, Wx1, bx1, Wx2, out_p);
    k_y0  <<<ROWS, 160>>>(h, s, Wh1, bh1);
    k_bn2 <<<HDIM, 256>>>(gh, bh);
    k_hout<<<ROWS, 128>>>(h, Wh2, bh2, out_h);
}

// round 10
// speedup vs baseline: 2.7780x; 1.1966x over previous
#include <cuda_runtime.h>
#include <cuda_fp16.h>
#include <math.h>
#include <stdint.h>

#define HDIM 72
#define NSEQ 256
#define BATCH 16
#define ROWS 4096          // BATCH*NSEQ
#define SDIM 13
#define HP 88              // half pitch: bank=(12g+tig)%32 -> conflict-free frags

// ---------------- device scratch (static, no runtime alloc) ----------------
__device__ float  d_A [ROWS*HDIM];
__device__ float  d_Bm[ROWS*HDIM];      // after k_scaleB: holds sc[c]*Bm
__device__ float  d_Rn[ROWS];
__device__ float  d_Rd[ROWS];
__device__ float  d_S5[5];              // Sn, Sd, Snn, Sdd, Snd
__device__ float  d_SA[BATCH*HDIM];
__device__ float  d_SB[BATCH*HDIM];
__device__ float  d_T6[6*HDIM];
__device__ float  d_bn1[2*HDIM];        // scale, shift
__device__ float  d_r1s[HDIM];          // sc*r1
__device__ float  d_r2s[HDIM];          // sc*r2
__device__ float  d_magg[ROWS*HDIM];
__device__ float  d_y0 [ROWS*HDIM];
__device__ float  d_bn2[2*HDIM];
__device__ __align__(16) __half d_W2h[HDIM*HP];   // We2^T fp16 [n][k], k padded
__device__ __align__(16) __half d_W1h[HDIM*HP];   // Wx1^T fp16 [n][k]

__device__ __forceinline__ float psif(float x){
    return copysignf(log1pf(fabsf(x)), x);
}
__device__ __forceinline__ float wsum(float v){
    v += __shfl_xor_sync(0xffffffffu, v, 16);
    v += __shfl_xor_sync(0xffffffffu, v, 8);
    v += __shfl_xor_sync(0xffffffffu, v, 4);
    v += __shfl_xor_sync(0xffffffffu, v, 2);
    v += __shfl_xor_sync(0xffffffffu, v, 1);
    return v;
}
__device__ __forceinline__ void mma16(float* c, uint32_t a0, uint32_t a1, uint32_t a2,
                                      uint32_t a3, uint32_t b0, uint32_t b1){
    asm volatile("mma.sync.aligned.m16n8k16.row.col.f32.f16.f16.f32 "
        "{%0,%1,%2,%3}, {%4,%5,%6,%7}, {%8,%9}, {%0,%1,%2,%3};"
        : "+f"(c[0]), "+f"(c[1]), "+f"(c[2]), "+f"(c[3])
        : "r"(a0), "r"(a1), "r"(a2), "r"(a3), "r"(b0), "r"(b1));
}

// ---------------- zero accumulators + fp16 weight transpose ----------------
__global__ void k_zero(const float* __restrict__ We2, const float* __restrict__ Wx1){
    int t = blockIdx.x*256 + threadIdx.x;    // grid 8 x 256 = 2048
    if (t < 5) d_S5[t] = 0.f;
    for (int i = t; i < 6*HDIM; i += 2048) d_T6[i] = 0.f;
    for (int i = t; i < HDIM*80; i += 2048){
        int k = i / HDIM, n = i - (i/HDIM)*HDIM;
        __half w2 = (k < HDIM) ? __float2half_rn(We2[k*HDIM + n]) : __half(0.f);
        __half w1 = (k < HDIM) ? __float2half_rn(Wx1[k*HDIM + n]) : __half(0.f);
        d_W2h[n*HP + k] = w2;
        d_W1h[n*HP + k] = w1;
    }
}

// ---------------- geometry moments (n,d recomputed later in k_main) ----------------
__global__ void k_geom(const float* __restrict__ p){
    int i = blockIdx.x, b = blockIdx.y;
    int row = b*NSEQ + i;
    int j = threadIdx.x;
    __shared__ float4 pi4s;
    __shared__ float red[8][5];
    if (j == 0) pi4s = reinterpret_cast<const float4*>(p)[row];
    __syncthreads();
    float4 pi = pi4s;
    float4 pj = reinterpret_cast<const float4*>(p)[b*NSEQ + j];
    float d0=pi.x-pj.x, d1=pi.y-pj.y, d2=pi.z-pj.z, d3=pi.w-pj.w;
    float n  = psif(d1*d1 + d2*d2 + d3*d3 - d0*d0);
    float dt = psif(pi.x*pj.x - pi.y*pj.y - pi.z*pj.z - pi.w*pj.w);
    float v0=wsum(n), v1=wsum(dt), v2=wsum(n*n), v3=wsum(dt*dt), v4=wsum(n*dt);
    int lane = j & 31, w = j >> 5;
    if (lane==0){ red[w][0]=v0; red[w][1]=v1; red[w][2]=v2; red[w][3]=v3; red[w][4]=v4; }
    __syncthreads();
    if (j == 0){
        float s0=0,s1=0,s2=0,s3=0,s4=0;
        for (int q=0;q<8;q++){ s0+=red[q][0]; s1+=red[q][1]; s2+=red[q][2]; s3+=red[q][3]; s4+=red[q][4]; }
        d_Rn[row]=s0; d_Rd[row]=s1;
        atomicAdd(&d_S5[0], s0); atomicAdd(&d_S5[1], s1);
        atomicAdd(&d_S5[2], s2); atomicAdd(&d_S5[3], s3); atomicAdd(&d_S5[4], s4);
    }
}

// ---------------- A/B: 8 rows per block ----------------
__global__ void k_AB(const float* __restrict__ h, const float* __restrict__ We1){
    __shared__ float Ws[144*HDIM];
    __shared__ float hs[8*HDIM];
    int t = threadIdx.x;   // 256
    int row0 = blockIdx.x*8;
    for (int idx=t; idx<144*HDIM; idx+=256) Ws[idx] = We1[idx];
    for (int idx=t; idx<8*HDIM; idx+=256)   hs[idx] = h[row0*HDIM + idx];
    __syncthreads();
    if (t < 144){
        bool isA = t < HDIM;
        int c = isA ? t : t - HDIM;
        const float* Wcol = Ws + (isA ? 0 : HDIM*HDIM) + c;
        #pragma unroll 2
        for (int r=0;r<8;r++){
            const float* hr = hs + r*HDIM;
            float acc = 0.f;
            #pragma unroll 8
            for (int k=0;k<HDIM;k++) acc = fmaf(hr[k], Wcol[k*HDIM], acc);
            if (isA) d_A [(row0+r)*HDIM + c] = acc;
            else     d_Bm[(row0+r)*HDIM + c] = acc;
        }
    }
}

// ---------------- per-channel moments of A,B ----------------
__global__ void k_mom(){
    int c = blockIdx.x, b = blockIdx.y;
    int t = threadIdx.x; // 256
    int r = b*NSEQ + t;
    float a  = d_A [r*HDIM + c];
    float bb = d_Bm[r*HDIM + c];
    float rn = d_Rn[r], rd = d_Rd[r];
    float v[8] = { a, bb, a*a, bb*bb, a*rn, a*rd, bb*rn, bb*rd };
    __shared__ float red[8][8];
    int lane = t & 31, w = t >> 5;
    #pragma unroll
    for (int q=0;q<8;q++){
        float s = wsum(v[q]);
        if (lane==0) red[w][q] = s;
    }
    __syncthreads();
    if (t == 0){
        float s[8];
        #pragma unroll
        for (int q=0;q<8;q++){ s[q]=0.f; for (int ww=0;ww<8;ww++) s[q]+=red[ww][q]; }
        d_SA[b*HDIM + c] = s[0];
        d_SB[b*HDIM + c] = s[1];
        atomicAdd(&d_T6[0*HDIM + c], s[2]);
        atomicAdd(&d_T6[1*HDIM + c], s[3]);
        atomicAdd(&d_T6[2*HDIM + c], s[4]);
        atomicAdd(&d_T6[3*HDIM + c], s[5]);
        atomicAdd(&d_T6[4*HDIM + c], s[6]);
        atomicAdd(&d_T6[5*HDIM + c], s[7]);
    }
}

// ---------------- BN1 finalize (exact algebra) + fold sc into r1,r2 ----------------
__global__ void k_bn1(const float* __restrict__ We1, const float* __restrict__ g1,
                      const float* __restrict__ b1){
    int c = threadIdx.x;
    if (c >= HDIM) return;
    float r1 = We1[144*HDIM + c], r2 = We1[145*HDIM + c];
    float SAt=0.f, SBt=0.f, cross=0.f;
    for (int b=0;b<BATCH;b++){
        float sa = d_SA[b*HDIM+c], sb = d_SB[b*HDIM+c];
        SAt += sa; SBt += sb; cross += sa*sb;
    }
    float Sn=d_S5[0], Sd=d_S5[1], Snn=d_S5[2], Sdd=d_S5[3], Snd=d_S5[4];
    float sumx  = 256.f*(SAt + SBt) + r1*Sn + r2*Sd;
    float sumx2 = 256.f*(d_T6[c] + d_T6[HDIM+c])
                + r1*r1*Snn + r2*r2*Sdd
                + 2.f*cross
                + 2.f*r1*(d_T6[2*HDIM+c] + d_T6[4*HDIM+c])
                + 2.f*r2*(d_T6[3*HDIM+c] + d_T6[5*HDIM+c])
                + 2.f*r1*r2*Snd;
    const float P = 1048576.f;
    float mu  = sumx / P;
    float var = sumx2 / P - mu*mu;
    float sc  = g1[c] * rsqrtf(var + 1e-5f);
    d_bn1[c]        = sc;
    d_bn1[HDIM + c] = b1[c] - mu*sc;
    d_r1s[c] = r1*sc;
    d_r2s[c] = r2*sc;
}

// ---------------- scale Bm in-place by sc (after moments are taken) ----------------
__global__ void k_scaleB(){
    int row = blockIdx.x*8 + threadIdx.y;
    int c = threadIdx.x;
    d_Bm[row*HDIM + c] *= d_bn1[c];
}

// ---------------- main pairwise kernel ----------------
// SMEM: Ts[256][HP] half | W2c[72][HP] half | W1c[72][HP] half | vectors
#define TS_OFF  0
#define TS_BYTES (256*HP*2)
#define W2_OFF  (TS_OFF + TS_BYTES)
#define W1_OFF  (W2_OFF + HDIM*HP*2)
#define VEC_OFF (W1_OFF + HDIM*HP*2)

struct KVecs {
    float Ash[HDIM], r1s[HDIM], r2s[HDIM];
    float be2v[HDIM], bx1v[HDIM], Wmv[HDIM], Wx2v[HDIM];
    float mg[HDIM];
    float aggred[8][4];
    float pis[4];
    float bmv;
};
#define KSMEM_TOTAL (VEC_OFF + (int)sizeof(KVecs))

__global__ __launch_bounds__(256, 2) void k_main(
    const float* __restrict__ p,
    const float* __restrict__ be2, const float* __restrict__ Wm,
    const float* __restrict__ bm,  const float* __restrict__ bx1,
    const float* __restrict__ Wx2, float* __restrict__ out_p)
{
    extern __shared__ unsigned char sm[];
    __half* Ts  = reinterpret_cast<__half*>(sm + TS_OFF);
    __half* W2c = reinterpret_cast<__half*>(sm + W2_OFF);
    __half* W1c = reinterpret_cast<__half*>(sm + W1_OFF);
    KVecs*  V   = reinterpret_cast<KVecs*>(sm + VEC_OFF);
    const int i = blockIdx.x, b = blockIdx.y;
    const int row = b*NSEQ + i;
    const int tid  = threadIdx.x;
    const int wid  = tid >> 5;       // 0..7
    const int lane = tid & 31;
    const int g    = lane >> 2;
    const int tig  = lane & 3;
    const int r0   = wid*32;         // warp's 32 rows

    // ---- init: copy pre-transposed fp16 weights, vectors, pad ----
    {
        uint4* dst2 = reinterpret_cast<uint4*>(W2c);
        uint4* dst1 = reinterpret_cast<uint4*>(W1c);
        const uint4* s2 = reinterpret_cast<const uint4*>(d_W2h);
        const uint4* s1 = reinterpret_cast<const uint4*>(d_W1h);
        for (int t = tid; t < HDIM*HP/8; t += 256){ dst2[t] = s2[t]; dst1[t] = s1[t]; }
    }
    *reinterpret_cast<uint4*>(Ts + tid*HP + 72) = make_uint4(0u,0u,0u,0u);  // K pad
    if (tid < HDIM){
        float sc = d_bn1[tid];
        V->Ash[tid]  = fmaf(d_A[row*HDIM + tid], sc, d_bn1[HDIM + tid]);
        V->r1s[tid]  = d_r1s[tid];
        V->r2s[tid]  = d_r2s[tid];
        V->be2v[tid] = be2[tid];
        V->bx1v[tid] = bx1[tid];
        V->Wmv[tid]  = Wm[tid];
        V->Wx2v[tid] = Wx2[tid];
        V->mg[tid]   = 0.f;
    }
    if (tid < 4)  V->pis[tid] = p[row*4 + tid];
    if (tid == 0) V->bmv = bm[0];
    __syncthreads();

    const float bmv = V->bmv;
    const float4 pis4 = *reinterpret_cast<const float4*>(V->pis);

    // ---- build all 256 rows: thread t builds row t ----
    {
        float4 pj = reinterpret_cast<const float4*>(p)[b*NSEQ + tid];
        float e0=pis4.x-pj.x, e1=pis4.y-pj.y, e2=pis4.z-pj.z, e3=pis4.w-pj.w;
        float nn = psif(e1*e1 + e2*e2 + e3*e3 - e0*e0);
        float dd = psif(pis4.x*pj.x - pis4.y*pj.y - pis4.z*pj.z - pis4.w*pj.w);
        const float4* B4 = reinterpret_cast<const float4*>(d_Bm + (b*NSEQ + tid)*HDIM);
        const float4* A4 = reinterpret_cast<const float4*>(V->Ash);
        const float4* U4 = reinterpret_cast<const float4*>(V->r1s);
        const float4* W4 = reinterpret_cast<const float4*>(V->r2s);
        #pragma unroll
        for (int q = 0; q < 18; ++q){
            float4 bv = B4[q];   // already sc-scaled
            float4 av = A4[q], uv = U4[q], wv = W4[q];
            float v0 = fmaxf(av.x + bv.x + nn*uv.x + dd*wv.x, 0.f);
            float v1 = fmaxf(av.y + bv.y + nn*uv.y + dd*wv.y, 0.f);
            float v2 = fmaxf(av.z + bv.z + nn*uv.z + dd*wv.z, 0.f);
            float v3 = fmaxf(av.w + bv.w + nn*uv.w + dd*wv.w, 0.f);
            __half2 hlo = __floats2half2_rn(v0, v1);
            __half2 hhi = __floats2half2_rn(v2, v3);
            uint2 u; u.x = *reinterpret_cast<uint32_t*>(&hlo); u.y = *reinterpret_cast<uint32_t*>(&hhi);
            *reinterpret_cast<uint2*>(Ts + tid*HP + q*4) = u;
        }
    }
    __syncwarp();

    float colsum[9][2];
    #pragma unroll
    for (int nt=0;nt<9;nt++){ colsum[nt][0]=0.f; colsum[nt][1]=0.f; }
    float agg0=0.f, agg1=0.f, agg2=0.f, agg3=0.f;
    float acc[2][9][4];

    // ================= GEMM1: acc = T @ We2 (2 chunks of 16 rows, B reused) ====
    #pragma unroll
    for (int ch=0;ch<2;ch++)
        #pragma unroll
        for (int nt=0;nt<9;nt++){ acc[ch][nt][0]=0.f; acc[ch][nt][1]=0.f; acc[ch][nt][2]=0.f; acc[ch][nt][3]=0.f; }
    #pragma unroll
    for (int kk=0;kk<5;kk++){
        int kb = kk*16 + 2*tig;
        uint32_t a[2][4];
        #pragma unroll
        for (int ch=0;ch<2;ch++){
            const __half* base = Ts + (r0 + ch*16 + g)*HP + kb;
            a[ch][0] = *reinterpret_cast<const uint32_t*>(base);
            a[ch][1] = *reinterpret_cast<const uint32_t*>(base + 8*HP);
            a[ch][2] = *reinterpret_cast<const uint32_t*>(base + 8);
            a[ch][3] = *reinterpret_cast<const uint32_t*>(base + 8*HP + 8);
        }
        #pragma unroll
        for (int nt=0;nt<9;nt++){
            uint32_t b0 = *reinterpret_cast<const uint32_t*>(W2c + (nt*8+g)*HP + kb);
            uint32_t b1 = *reinterpret_cast<const uint32_t*>(W2c + (nt*8+g)*HP + kb + 8);
            mma16(acc[0][nt], a[0][0], a[0][1], a[0][2], a[0][3], b0, b1);
            mma16(acc[1][nt], a[1][0], a[1][1], a[1][2], a[1][3], b0, b1);
        }
    }
    __syncwarp();

    // ---- epi1: m = relu(acc+be2); w = sigmoid(m.Wm+bm); wm = m*w -> Ts ----
    #pragma unroll
    for (int ch=0;ch<2;ch++){
        float dot0 = 0.f, dot1 = 0.f;
        #pragma unroll
        for (int nt=0;nt<9;nt++){
            int cb = nt*8 + 2*tig;
            float2 bb = *reinterpret_cast<const float2*>(V->be2v + cb);
            float2 wm2 = *reinterpret_cast<const float2*>(V->Wmv + cb);
            float m0 = fmaxf(acc[ch][nt][0] + bb.x, 0.f);
            float m1 = fmaxf(acc[ch][nt][1] + bb.y, 0.f);
            float m2 = fmaxf(acc[ch][nt][2] + bb.x, 0.f);
            float m3 = fmaxf(acc[ch][nt][3] + bb.y, 0.f);
            acc[ch][nt][0]=m0; acc[ch][nt][1]=m1; acc[ch][nt][2]=m2; acc[ch][nt][3]=m3;
            dot0 = fmaf(m0, wm2.x, fmaf(m1, wm2.y, dot0));
            dot1 = fmaf(m2, wm2.x, fmaf(m3, wm2.y, dot1));
        }
        dot0 += __shfl_xor_sync(0xffffffffu, dot0, 1);
        dot0 += __shfl_xor_sync(0xffffffffu, dot0, 2);
        dot1 += __shfl_xor_sync(0xffffffffu, dot1, 1);
        dot1 += __shfl_xor_sync(0xffffffffu, dot1, 2);
        float w0 = 1.f / (1.f + expf(-(dot0 + bmv)));
        float w1 = 1.f / (1.f + expf(-(dot1 + bmv)));
        const int rl = r0 + ch*16 + g;
        #pragma unroll
        for (int nt=0;nt<9;nt++){
            float l0 = acc[ch][nt][0]*w0;
            float l1 = acc[ch][nt][1]*w0;
            float h0 = acc[ch][nt][2]*w1;
            float h1 = acc[ch][nt][3]*w1;
            colsum[nt][0] += l0 + h0;
            colsum[nt][1] += l1 + h1;
            int cb = nt*8 + 2*tig;
            __half2 lo = __floats2half2_rn(l0, l1);
            __half2 hi = __floats2half2_rn(h0, h1);
            *reinterpret_cast<uint32_t*>(Ts + rl*HP + cb)       = *reinterpret_cast<uint32_t*>(&lo);
            *reinterpret_cast<uint32_t*>(Ts + (rl+8)*HP + cb)   = *reinterpret_cast<uint32_t*>(&hi);
        }
    }
    __syncwarp();

    // ================= GEMM2: acc = wm @ Wx1 =================
    #pragma unroll
    for (int ch=0;ch<2;ch++)
        #pragma unroll
        for (int nt=0;nt<9;nt++){ acc[ch][nt][0]=0.f; acc[ch][nt][1]=0.f; acc[ch][nt][2]=0.f; acc[ch][nt][3]=0.f; }
    #pragma unroll
    for (int kk=0;kk<5;kk++){
        int kb = kk*16 + 2*tig;
        uint32_t a[2][4];
        #pragma unroll
        for (int ch=0;ch<2;ch++){
            const __half* base = Ts + (r0 + ch*16 + g)*HP + kb;
            a[ch][0] = *reinterpret_cast<const uint32_t*>(base);
            a[ch][1] = *reinterpret_cast<const uint32_t*>(base + 8*HP);
            a[ch][2] = *reinterpret_cast<const uint32_t*>(base + 8);
            a[ch][3] = *reinterpret_cast<const uint32_t*>(base + 8*HP + 8);
        }
        #pragma unroll
        for (int nt=0;nt<9;nt++){
            uint32_t b0 = *reinterpret_cast<const uint32_t*>(W1c + (nt*8+g)*HP + kb);
            uint32_t b1 = *reinterpret_cast<const uint32_t*>(W1c + (nt*8+g)*HP + kb + 8);
            mma16(acc[0][nt], a[0][0], a[0][1], a[0][2], a[0][3], b0, b1);
            mma16(acc[1][nt], a[1][0], a[1][1], a[1][2], a[1][3], b0, b1);
        }
    }

    // ---- epi2: u = relu(acc+bx1); xw = u.Wx2; tig0 lanes do their rows' aggs ----
    #pragma unroll
    for (int ch=0;ch<2;ch++){
        float px0 = 0.f, px1 = 0.f;
        #pragma unroll
        for (int nt=0;nt<9;nt++){
            int cb = nt*8 + 2*tig;
            float2 bb = *reinterpret_cast<const float2*>(V->bx1v + cb);
            float2 wx = *reinterpret_cast<const float2*>(V->Wx2v + cb);
            float u0 = fmaxf(acc[ch][nt][0] + bb.x, 0.f);
            float u1 = fmaxf(acc[ch][nt][1] + bb.y, 0.f);
            float u2 = fmaxf(acc[ch][nt][2] + bb.x, 0.f);
            float u3 = fmaxf(acc[ch][nt][3] + bb.y, 0.f);
            px0 = fmaf(u0, wx.x, fmaf(u1, wx.y, px0));
            px1 = fmaf(u2, wx.x, fmaf(u3, wx.y, px1));
        }
        px0 += __shfl_xor_sync(0xffffffffu, px0, 1);
        px0 += __shfl_xor_sync(0xffffffffu, px0, 2);
        px1 += __shfl_xor_sync(0xffffffffu, px1, 1);
        px1 += __shfl_xor_sync(0xffffffffu, px1, 2);
        if (tig == 0){
            int jl = r0 + ch*16 + g;
            float4 pj = reinterpret_cast<const float4*>(p)[b*NSEQ + jl];
            agg0 += fminf(fmaxf((pis4.x - pj.x)*px0, -100.f), 100.f);
            agg1 += fminf(fmaxf((pis4.y - pj.y)*px0, -100.f), 100.f);
            agg2 += fminf(fmaxf((pis4.z - pj.z)*px0, -100.f), 100.f);
            agg3 += fminf(fmaxf((pis4.w - pj.w)*px0, -100.f), 100.f);
            float4 ph = reinterpret_cast<const float4*>(p)[b*NSEQ + jl + 8];
            agg0 += fminf(fmaxf((pis4.x - ph.x)*px1, -100.f), 100.f);
            agg1 += fminf(fmaxf((pis4.y - ph.y)*px1, -100.f), 100.f);
            agg2 += fminf(fmaxf((pis4.z - ph.z)*px1, -100.f), 100.f);
            agg3 += fminf(fmaxf((pis4.w - ph.w)*px1, -100.f), 100.f);
        }
    }

    // ---- magg: reduce colsum over g-lanes, atomic into V->mg ----
    #pragma unroll
    for (int nt=0;nt<9;nt++)
        #pragma unroll
        for (int d=0;d<2;d++){
            float v = colsum[nt][d];
            v += __shfl_xor_sync(0xffffffffu, v, 4);
            v += __shfl_xor_sync(0xffffffffu, v, 8);
            v += __shfl_xor_sync(0xffffffffu, v, 16);
            if (g == 0) atomicAdd(&V->mg[nt*8 + 2*tig + d], v);
        }
    // ---- agg reduce across warps ----
    {
        float s0=wsum(agg0), s1=wsum(agg1), s2=wsum(agg2), s3=wsum(agg3);
        if (lane==0){ V->aggred[wid][0]=s0; V->aggred[wid][1]=s1; V->aggred[wid][2]=s2; V->aggred[wid][3]=s3; }
    }
    __syncthreads();
    if (tid < HDIM) d_magg[row*HDIM + tid] = V->mg[tid];
    if (tid < 4){
        float s = 0.f;
        #pragma unroll
        for (int w=0;w<8;w++) s += V->aggred[w][tid];
        out_p[row*4 + tid] = V->pis[tid] + (s * (1.f/256.f)) * 0.001f;
    }
}

// ---------------- h-path: y0 = [h,magg,s] @ Wh1 + bh1 (8 rows/block) ----------------
__global__ void k_y0(const float* __restrict__ h, const float* __restrict__ s,
                     const float* __restrict__ Wh1, const float* __restrict__ bh1){
    __shared__ float Wh1s[(2*HDIM+SDIM)*HDIM];
    __shared__ float hin[2*HDIM + SDIM];
    int t = threadIdx.x;   // 160
    int row0 = blockIdx.x*8;
    for (int idx=t; idx<(2*HDIM+SDIM)*HDIM; idx+=160) Wh1s[idx] = Wh1[idx];
    for (int r=0;r<8;r++){
        int row = row0 + r;
        __syncthreads();
        if (t < HDIM)               hin[t] = h[row*HDIM + t];
        else if (t < 2*HDIM)        hin[t] = d_magg[row*HDIM + (t - HDIM)];
        else if (t < 2*HDIM + SDIM) hin[t] = s[row*SDIM + (t - 2*HDIM)];
        __syncthreads();
        if (t < HDIM){
            float acc = bh1[t];
            #pragma unroll 8
            for (int k=0;k<2*HDIM+SDIM;k++) acc = fmaf(hin[k], Wh1s[k*HDIM + t], acc);
            d_y0[row*HDIM + t] = acc;
        }
    }
}

__global__ void k_bn2(const float* __restrict__ gh, const float* __restrict__ bh){
    int c = blockIdx.x;
    int t = threadIdx.x; // 256
    float sum=0.f, sq=0.f;
    for (int r=t; r<ROWS; r+=256){
        float v = d_y0[r*HDIM + c];
        sum += v; sq += v*v;
    }
    __shared__ float red[8][2];
    float s0 = wsum(sum), s1 = wsum(sq);
    int lane=t&31, w=t>>5;
    if (lane==0){ red[w][0]=s0; red[w][1]=s1; }
    __syncthreads();
    if (t==0){
        float a=0.f,bb=0.f;
        for (int q=0;q<8;q++){ a+=red[q][0]; bb+=red[q][1]; }
        float mu  = a / 4096.f;
        float var = bb / 4096.f - mu*mu;
        float sc  = gh[c] * rsqrtf(var + 1e-5f);
        d_bn2[c]        = sc;
        d_bn2[HDIM + c] = bh[c] - mu*sc;
    }
}

__global__ void k_hout(const float* __restrict__ h, const float* __restrict__ Wh2,
                       const float* __restrict__ bh2, float* __restrict__ out_h){
    __shared__ float W[HDIM*HDIM];
    __shared__ float yr[HDIM];
    int t = threadIdx.x; // 128
    int row0 = blockIdx.x*8;
    for (int idx=t; idx<HDIM*HDIM; idx+=128) W[idx] = Wh2[idx];
    for (int r=0;r<8;r++){
        int row = row0 + r;
        __syncthreads();
        if (t < HDIM) yr[t] = fmaxf(fmaf(d_y0[row*HDIM+t], d_bn2[t], d_bn2[HDIM+t]), 0.f);
        __syncthreads();
        if (t < HDIM){
            float acc = bh2[t];
            #pragma unroll 8
            for (int k=0;k<HDIM;k++) acc = fmaf(yr[k], W[k*HDIM + t], acc);
            out_h[row*HDIM + t] = h[row*HDIM + t] + acc;
        }
    }
}

// ---------------- launch ----------------
extern "C" void kernel_launch(void* const* d_in, const int* in_sizes, int n_in,
                              void* d_out, int out_size){
    const float* h   = (const float*)d_in[0];
    const float* p   = (const float*)d_in[1];
    const float* s   = (const float*)d_in[2];
    const float* We1 = (const float*)d_in[3];
    const float* g1  = (const float*)d_in[4];
    const float* b1  = (const float*)d_in[5];
    const float* We2 = (const float*)d_in[6];
    const float* be2 = (const float*)d_in[7];
    const float* Wm  = (const float*)d_in[8];
    const float* bm  = (const float*)d_in[9];
    const float* Wx1 = (const float*)d_in[10];
    const float* bx1 = (const float*)d_in[11];
    const float* Wx2 = (const float*)d_in[12];
    const float* Wh1 = (const float*)d_in[13];
    const float* bh1 = (const float*)d_in[14];
    const float* gh  = (const float*)d_in[15];
    const float* bh  = (const float*)d_in[16];
    const float* Wh2 = (const float*)d_in[17];
    const float* bh2 = (const float*)d_in[18];
    float* out   = (float*)d_out;
    float* out_h = out;                 // (B,N,H) first
    float* out_p = out + ROWS*HDIM;     // then (B,N,4)

    cudaFuncSetAttribute(k_main, cudaFuncAttributeMaxDynamicSharedMemorySize, KSMEM_TOTAL);

    k_zero  <<<8, 256>>>(We2, Wx1);
    k_geom  <<<dim3(NSEQ, BATCH), NSEQ>>>(p);
    k_AB    <<<ROWS/8, 256>>>(h, We1);
    k_mom   <<<dim3(HDIM, BATCH), 256>>>();
    k_bn1   <<<1, HDIM>>>(We1, g1, b1);
    k_scaleB<<<ROWS/8, dim3(HDIM, 8)>>>();
    k_main  <<<dim3(NSEQ, BATCH), 256, KSMEM_TOTAL>>>(p, be2, Wm, bm, bx1, Wx2, out_p);
    k_y0    <<<ROWS/8, 160>>>(h, s, Wh1, bh1);
    k_bn2   <<<HDIM, 256>>>(gh, bh);
    k_hout  <<<ROWS/8, 128>>>(h, Wh2, bh2, out_h);
}

// round 12
// speedup vs baseline: 2.8655x; 1.0315x over previous
#include <cuda_runtime.h>
#include <cuda_fp16.h>
#include <math.h>
#include <stdint.h>

#define HDIM 72
#define NSEQ 256
#define BATCH 16
#define ROWS 4096          // BATCH*NSEQ
#define SDIM 13
#define HP 88              // half pitch: row-start bank (44r)%32 distinct -> ldmatrix conflict-free

// ---------------- device scratch (static, no runtime alloc) ----------------
__device__ float  d_A [ROWS*HDIM];
__device__ float  d_Bm[ROWS*HDIM];      // UNSCALED (scale folded into k_main build)
__device__ float  d_Rn[ROWS];
__device__ float  d_Rd[ROWS];
__device__ float  d_S5[5];              // Sn, Sd, Snn, Sdd, Snd
__device__ float  d_SA[BATCH*HDIM];
__device__ float  d_SB[BATCH*HDIM];
__device__ float  d_T6[6*HDIM];
__device__ float  d_bn1[2*HDIM];        // scale, shift
__device__ float  d_r1s[HDIM];          // sc*r1
__device__ float  d_r2s[HDIM];          // sc*r2
__device__ float  d_magg[ROWS*HDIM];
__device__ float  d_y0 [ROWS*HDIM];
__device__ float  d_bn2[2*HDIM];
__device__ float  d_bn2acc[2*HDIM];     // sum, sumsq of y0 per channel
__device__ __align__(16) __half d_W2h[HDIM*HP];   // We2^T fp16 [n][k], k padded
__device__ __align__(16) __half d_W1h[HDIM*HP];   // Wx1^T fp16 [n][k]

__device__ __forceinline__ float psif(float x){
    return copysignf(log1pf(fabsf(x)), x);
}
__device__ __forceinline__ float wsum(float v){
    v += __shfl_xor_sync(0xffffffffu, v, 16);
    v += __shfl_xor_sync(0xffffffffu, v, 8);
    v += __shfl_xor_sync(0xffffffffu, v, 4);
    v += __shfl_xor_sync(0xffffffffu, v, 2);
    v += __shfl_xor_sync(0xffffffffu, v, 1);
    return v;
}
__device__ __forceinline__ uint32_t smem_u32(const void* p){
    uint32_t a;
    asm("{ .reg .u64 t; cvta.to.shared.u64 t, %1; cvt.u32.u64 %0, t; }" : "=r"(a) : "l"(p));
    return a;
}
__device__ __forceinline__ void mma16(float* c, uint32_t a0, uint32_t a1, uint32_t a2,
                                      uint32_t a3, uint32_t b0, uint32_t b1){
    asm volatile("mma.sync.aligned.m16n8k16.row.col.f32.f16.f16.f32 "
        "{%0,%1,%2,%3}, {%4,%5,%6,%7}, {%8,%9}, {%0,%1,%2,%3};"
        : "+f"(c[0]), "+f"(c[1]), "+f"(c[2]), "+f"(c[3])
        : "r"(a0), "r"(a1), "r"(a2), "r"(a3), "r"(b0), "r"(b1));
}
__device__ __forceinline__ void ldsm_x4(uint32_t& r0, uint32_t& r1, uint32_t& r2,
                                        uint32_t& r3, uint32_t addr){
    asm volatile("ldmatrix.sync.aligned.m8n8.x4.shared.b16 {%0,%1,%2,%3}, [%4];"
        : "=r"(r0), "=r"(r1), "=r"(r2), "=r"(r3) : "r"(addr));
}
__device__ __forceinline__ void ldsm_x2(uint32_t& r0, uint32_t& r1, uint32_t addr){
    asm volatile("ldmatrix.sync.aligned.m8n8.x2.shared.b16 {%0,%1}, [%2];"
        : "=r"(r0), "=r"(r1) : "r"(addr));
}

// ---------------- zero accumulators + fp16 weight transpose ----------------
__global__ void k_zero(const float* __restrict__ We2, const float* __restrict__ Wx1){
    int t = blockIdx.x*256 + threadIdx.x;    // grid 8 x 256 = 2048
    if (t < 5) d_S5[t] = 0.f;
    for (int i = t; i < 6*HDIM; i += 2048) d_T6[i] = 0.f;
    for (int i = t; i < 2*HDIM; i += 2048) d_bn2acc[i] = 0.f;
    for (int i = t; i < HDIM*80; i += 2048){
        int k = i / HDIM, n = i - (i/HDIM)*HDIM;
        __half w2 = (k < HDIM) ? __float2half_rn(We2[k*HDIM + n]) : __half(0.f);
        __half w1 = (k < HDIM) ? __float2half_rn(Wx1[k*HDIM + n]) : __half(0.f);
        d_W2h[n*HP + k] = w2;
        d_W1h[n*HP + k] = w1;
    }
}

// ---------------- geometry moments ----------------
__global__ void k_geom(const float* __restrict__ p){
    int i = blockIdx.x, b = blockIdx.y;
    int row = b*NSEQ + i;
    int j = threadIdx.x;
    __shared__ float4 pi4s;
    __shared__ float red[8][5];
    if (j == 0) pi4s = reinterpret_cast<const float4*>(p)[row];
    __syncthreads();
    float4 pi = pi4s;
    float4 pj = reinterpret_cast<const float4*>(p)[b*NSEQ + j];
    float d0=pi.x-pj.x, d1=pi.y-pj.y, d2=pi.z-pj.z, d3=pi.w-pj.w;
    float n  = psif(d1*d1 + d2*d2 + d3*d3 - d0*d0);
    float dt = psif(pi.x*pj.x - pi.y*pj.y - pi.z*pj.z - pi.w*pj.w);
    float v0=wsum(n), v1=wsum(dt), v2=wsum(n*n), v3=wsum(dt*dt), v4=wsum(n*dt);
    int lane = j & 31, w = j >> 5;
    if (lane==0){ red[w][0]=v0; red[w][1]=v1; red[w][2]=v2; red[w][3]=v3; red[w][4]=v4; }
    __syncthreads();
    if (j == 0){
        float s0=0,s1=0,s2=0,s3=0,s4=0;
        for (int q=0;q<8;q++){ s0+=red[q][0]; s1+=red[q][1]; s2+=red[q][2]; s3+=red[q][3]; s4+=red[q][4]; }
        d_Rn[row]=s0; d_Rd[row]=s1;
        atomicAdd(&d_S5[0], s0); atomicAdd(&d_S5[1], s1);
        atomicAdd(&d_S5[2], s2); atomicAdd(&d_S5[3], s3); atomicAdd(&d_S5[4], s4);
    }
}

// ---------------- A/B: 8 rows per block ----------------
__global__ void k_AB(const float* __restrict__ h, const float* __restrict__ We1){
    __shared__ float Ws[144*HDIM];
    __shared__ float hs[8*HDIM];
    int t = threadIdx.x;   // 256
    int row0 = blockIdx.x*8;
    for (int idx=t; idx<144*HDIM; idx+=256) Ws[idx] = We1[idx];
    for (int idx=t; idx<8*HDIM; idx+=256)   hs[idx] = h[row0*HDIM + idx];
    __syncthreads();
    if (t < 144){
        bool isA = t < HDIM;
        int c = isA ? t : t - HDIM;
        const float* Wcol = Ws + (isA ? 0 : HDIM*HDIM) + c;
        #pragma unroll 2
        for (int r=0;r<8;r++){
            const float* hr = hs + r*HDIM;
            float acc = 0.f;
            #pragma unroll 8
            for (int k=0;k<HDIM;k++) acc = fmaf(hr[k], Wcol[k*HDIM], acc);
            if (isA) d_A [(row0+r)*HDIM + c] = acc;
            else     d_Bm[(row0+r)*HDIM + c] = acc;
        }
    }
}

// ---------------- per-channel moments of A,B ----------------
__global__ void k_mom(){
    int c = blockIdx.x, b = blockIdx.y;
    int t = threadIdx.x; // 256
    int r = b*NSEQ + t;
    float a  = d_A [r*HDIM + c];
    float bb = d_Bm[r*HDIM + c];
    float rn = d_Rn[r], rd = d_Rd[r];
    float v[8] = { a, bb, a*a, bb*bb, a*rn, a*rd, bb*rn, bb*rd };
    __shared__ float red[8][8];
    int lane = t & 31, w = t >> 5;
    #pragma unroll
    for (int q=0;q<8;q++){
        float s = wsum(v[q]);
        if (lane==0) red[w][q] = s;
    }
    __syncthreads();
    if (t == 0){
        float s[8];
        #pragma unroll
        for (int q=0;q<8;q++){ s[q]=0.f; for (int ww=0;ww<8;ww++) s[q]+=red[ww][q]; }
        d_SA[b*HDIM + c] = s[0];
        d_SB[b*HDIM + c] = s[1];
        atomicAdd(&d_T6[0*HDIM + c], s[2]);
        atomicAdd(&d_T6[1*HDIM + c], s[3]);
        atomicAdd(&d_T6[2*HDIM + c], s[4]);
        atomicAdd(&d_T6[3*HDIM + c], s[5]);
        atomicAdd(&d_T6[4*HDIM + c], s[6]);
        atomicAdd(&d_T6[5*HDIM + c], s[7]);
    }
}

// ---------------- BN1 finalize (exact algebra) + fold sc into r1,r2 ----------------
__global__ void k_bn1(const float* __restrict__ We1, const float* __restrict__ g1,
                      const float* __restrict__ b1){
    int c = threadIdx.x;
    if (c >= HDIM) return;
    float r1 = We1[144*HDIM + c], r2 = We1[145*HDIM + c];
    float SAt=0.f, SBt=0.f, cross=0.f;
    for (int b=0;b<BATCH;b++){
        float sa = d_SA[b*HDIM+c], sb = d_SB[b*HDIM+c];
        SAt += sa; SBt += sb; cross += sa*sb;
    }
    float Sn=d_S5[0], Sd=d_S5[1], Snn=d_S5[2], Sdd=d_S5[3], Snd=d_S5[4];
    float sumx  = 256.f*(SAt + SBt) + r1*Sn + r2*Sd;
    float sumx2 = 256.f*(d_T6[c] + d_T6[HDIM+c])
                + r1*r1*Snn + r2*r2*Sdd
                + 2.f*cross
                + 2.f*r1*(d_T6[2*HDIM+c] + d_T6[4*HDIM+c])
                + 2.f*r2*(d_T6[3*HDIM+c] + d_T6[5*HDIM+c])
                + 2.f*r1*r2*Snd;
    const float P = 1048576.f;
    float mu  = sumx / P;
    float var = sumx2 / P - mu*mu;
    float sc  = g1[c] * rsqrtf(var + 1e-5f);
    d_bn1[c]        = sc;
    d_bn1[HDIM + c] = b1[c] - mu*sc;
    d_r1s[c] = r1*sc;
    d_r2s[c] = r2*sc;
}

// ---------------- main pairwise kernel ----------------
// SMEM: Ts[256][HP] half | W2c[72][HP] half | W1c[72][HP] half | vectors
#define TS_OFF  0
#define TS_BYTES (256*HP*2)
#define W2_OFF  (TS_OFF + TS_BYTES)
#define W1_OFF  (W2_OFF + HDIM*HP*2)
#define VEC_OFF (W1_OFF + HDIM*HP*2)

struct KVecs {
    float Ash[HDIM], Scv[HDIM], r1s[HDIM], r2s[HDIM];
    float be2v[HDIM], bx1v[HDIM], Wmv[HDIM], Wx2v[HDIM];
    float mg[HDIM];
    float aggred[8][4];
    float pis[4];
    float bmv;
};
#define KSMEM_TOTAL (VEC_OFF + (int)sizeof(KVecs))

__global__ __launch_bounds__(256, 2) void k_main(
    const float* __restrict__ p,
    const float* __restrict__ be2, const float* __restrict__ Wm,
    const float* __restrict__ bm,  const float* __restrict__ bx1,
    const float* __restrict__ Wx2, float* __restrict__ out_p)
{
    extern __shared__ unsigned char sm[];
    __half* Ts  = reinterpret_cast<__half*>(sm + TS_OFF);
    __half* W2c = reinterpret_cast<__half*>(sm + W2_OFF);
    __half* W1c = reinterpret_cast<__half*>(sm + W1_OFF);
    KVecs*  V   = reinterpret_cast<KVecs*>(sm + VEC_OFF);
    const int i = blockIdx.x, b = blockIdx.y;
    const int row = b*NSEQ + i;
    const int tid  = threadIdx.x;
    const int wid  = tid >> 5;       // 0..7
    const int lane = tid & 31;
    const int g    = lane >> 2;
    const int tig  = lane & 3;
    const int r0   = wid*32;         // warp's 32 rows

    // ---- init: copy pre-transposed fp16 weights, vectors, pad ----
    {
        uint4* dst2 = reinterpret_cast<uint4*>(W2c);
        uint4* dst1 = reinterpret_cast<uint4*>(W1c);
        const uint4* s2 = reinterpret_cast<const uint4*>(d_W2h);
        const uint4* s1 = reinterpret_cast<const uint4*>(d_W1h);
        for (int t = tid; t < HDIM*HP/8; t += 256){ dst2[t] = s2[t]; dst1[t] = s1[t]; }
    }
    *reinterpret_cast<uint4*>(Ts + tid*HP + 72) = make_uint4(0u,0u,0u,0u);  // K pad
    if (tid < HDIM){
        float sc = d_bn1[tid];
        V->Ash[tid]  = fmaf(d_A[row*HDIM + tid], sc, d_bn1[HDIM + tid]);
        V->Scv[tid]  = sc;
        V->r1s[tid]  = d_r1s[tid];
        V->r2s[tid]  = d_r2s[tid];
        V->be2v[tid] = be2[tid];
        V->bx1v[tid] = bx1[tid];
        V->Wmv[tid]  = Wm[tid];
        V->Wx2v[tid] = Wx2[tid];
        V->mg[tid]   = 0.f;
    }
    if (tid < 4)  V->pis[tid] = p[row*4 + tid];
    if (tid == 0) V->bmv = bm[0];
    __syncthreads();

    const float bmv = V->bmv;
    const float4 pis4 = *reinterpret_cast<const float4*>(V->pis);

    // ---- build all 256 rows: thread t builds row t (scale of Bm folded in) ----
    {
        float4 pj = reinterpret_cast<const float4*>(p)[b*NSEQ + tid];
        float e0=pis4.x-pj.x, e1=pis4.y-pj.y, e2=pis4.z-pj.z, e3=pis4.w-pj.w;
        float nn = psif(e1*e1 + e2*e2 + e3*e3 - e0*e0);
        float dd = psif(pis4.x*pj.x - pis4.y*pj.y - pis4.z*pj.z - pis4.w*pj.w);
        const float4* B4 = reinterpret_cast<const float4*>(d_Bm + (b*NSEQ + tid)*HDIM);
        const float4* A4 = reinterpret_cast<const float4*>(V->Ash);
        const float4* S4 = reinterpret_cast<const float4*>(V->Scv);
        const float4* U4 = reinterpret_cast<const float4*>(V->r1s);
        const float4* W4 = reinterpret_cast<const float4*>(V->r2s);
        #pragma unroll
        for (int q = 0; q < 18; ++q){
            float4 bv = B4[q];
            float4 av = A4[q], sv = S4[q], uv = U4[q], wv = W4[q];
            float v0 = fmaxf(fmaf(sv.x, bv.x, av.x) + nn*uv.x + dd*wv.x, 0.f);
            float v1 = fmaxf(fmaf(sv.y, bv.y, av.y) + nn*uv.y + dd*wv.y, 0.f);
            float v2 = fmaxf(fmaf(sv.z, bv.z, av.z) + nn*uv.z + dd*wv.z, 0.f);
            float v3 = fmaxf(fmaf(sv.w, bv.w, av.w) + nn*uv.w + dd*wv.w, 0.f);
            __half2 hlo = __floats2half2_rn(v0, v1);
            __half2 hhi = __floats2half2_rn(v2, v3);
            uint2 u; u.x = *reinterpret_cast<uint32_t*>(&hlo); u.y = *reinterpret_cast<uint32_t*>(&hhi);
            *reinterpret_cast<uint2*>(Ts + tid*HP + q*4) = u;
        }
    }
    __syncwarp();

    // ldmatrix addresses
    const int lr  = lane & 15;
    const int kh  = (lane & 16) ? 8 : 0;
    const uint32_t aAddr0 = smem_u32(Ts) + (uint32_t)(((r0 + lr)*HP + kh)*2);
    const uint32_t aAddr1 = aAddr0 + 16*HP*2;
    const int bl  = lane & 7;
    const int bko = (lane & 8) ? 8 : 0;
    const uint32_t b2Addr = smem_u32(W2c) + (uint32_t)((bl*HP + bko)*2);
    const uint32_t b1Addr = smem_u32(W1c) + (uint32_t)((bl*HP + bko)*2);

    float colsum[9][2];
    #pragma unroll
    for (int nt=0;nt<9;nt++){ colsum[nt][0]=0.f; colsum[nt][1]=0.f; }
    float agg0=0.f, agg1=0.f, agg2=0.f, agg3=0.f;
    float acc[2][9][4];

    // ================= GEMM1: acc = T @ We2 =================
    #pragma unroll
    for (int ch=0;ch<2;ch++)
        #pragma unroll
        for (int nt=0;nt<9;nt++){ acc[ch][nt][0]=0.f; acc[ch][nt][1]=0.f; acc[ch][nt][2]=0.f; acc[ch][nt][3]=0.f; }
    #pragma unroll
    for (int kk=0;kk<5;kk++){
        uint32_t a[2][4];
        ldsm_x4(a[0][0], a[0][1], a[0][2], a[0][3], aAddr0 + kk*32);
        ldsm_x4(a[1][0], a[1][1], a[1][2], a[1][3], aAddr1 + kk*32);
        #pragma unroll
        for (int nt=0;nt<9;nt++){
            uint32_t b0, b1;
            ldsm_x2(b0, b1, b2Addr + nt*(8*HP*2) + kk*32);
            mma16(acc[0][nt], a[0][0], a[0][1], a[0][2], a[0][3], b0, b1);
            mma16(acc[1][nt], a[1][0], a[1][1], a[1][2], a[1][3], b0, b1);
        }
    }
    __syncwarp();

    // ---- epi1: m = relu(acc+be2); w = sigmoid(m.Wm+bm); wm = m*w -> Ts ----
    #pragma unroll
    for (int ch=0;ch<2;ch++){
        float dot0 = 0.f, dot1 = 0.f;
        #pragma unroll
        for (int nt=0;nt<9;nt++){
            int cb = nt*8 + 2*tig;
            float2 bb = *reinterpret_cast<const float2*>(V->be2v + cb);
            float2 wm2 = *reinterpret_cast<const float2*>(V->Wmv + cb);
            float m0 = fmaxf(acc[ch][nt][0] + bb.x, 0.f);
            float m1 = fmaxf(acc[ch][nt][1] + bb.y, 0.f);
            float m2 = fmaxf(acc[ch][nt][2] + bb.x, 0.f);
            float m3 = fmaxf(acc[ch][nt][3] + bb.y, 0.f);
            acc[ch][nt][0]=m0; acc[ch][nt][1]=m1; acc[ch][nt][2]=m2; acc[ch][nt][3]=m3;
            dot0 = fmaf(m0, wm2.x, fmaf(m1, wm2.y, dot0));
            dot1 = fmaf(m2, wm2.x, fmaf(m3, wm2.y, dot1));
        }
        dot0 += __shfl_xor_sync(0xffffffffu, dot0, 1);
        dot0 += __shfl_xor_sync(0xffffffffu, dot0, 2);
        dot1 += __shfl_xor_sync(0xffffffffu, dot1, 1);
        dot1 += __shfl_xor_sync(0xffffffffu, dot1, 2);
        float w0 = 1.f / (1.f + expf(-(dot0 + bmv)));
        float w1 = 1.f / (1.f + expf(-(dot1 + bmv)));
        const int rl = r0 + ch*16 + g;
        #pragma unroll
        for (int nt=0;nt<9;nt++){
            float l0 = acc[ch][nt][0]*w0;
            float l1 = acc[ch][nt][1]*w0;
            float h0 = acc[ch][nt][2]*w1;
            float h1 = acc[ch][nt][3]*w1;
            colsum[nt][0] += l0 + h0;
            colsum[nt][1] += l1 + h1;
            int cb = nt*8 + 2*tig;
            __half2 lo = __floats2half2_rn(l0, l1);
            __half2 hi = __floats2half2_rn(h0, h1);
            *reinterpret_cast<uint32_t*>(Ts + rl*HP + cb)     = *reinterpret_cast<uint32_t*>(&lo);
            *reinterpret_cast<uint32_t*>(Ts + (rl+8)*HP + cb) = *reinterpret_cast<uint32_t*>(&hi);
        }
    }
    __syncwarp();

    // ================= GEMM2: acc = wm @ Wx1 =================
    #pragma unroll
    for (int ch=0;ch<2;ch++)
        #pragma unroll
        for (int nt=0;nt<9;nt++){ acc[ch][nt][0]=0.f; acc[ch][nt][1]=0.f; acc[ch][nt][2]=0.f; acc[ch][nt][3]=0.f; }
    #pragma unroll
    for (int kk=0;kk<5;kk++){
        uint32_t a[2][4];
        ldsm_x4(a[0][0], a[0][1], a[0][2], a[0][3], aAddr0 + kk*32);
        ldsm_x4(a[1][0], a[1][1], a[1][2], a[1][3], aAddr1 + kk*32);
        #pragma unroll
        for (int nt=0;nt<9;nt++){
            uint32_t b0, b1;
            ldsm_x2(b0, b1, b1Addr + nt*(8*HP*2) + kk*32);
            mma16(acc[0][nt], a[0][0], a[0][1], a[0][2], a[0][3], b0, b1);
            mma16(acc[1][nt], a[1][0], a[1][1], a[1][2], a[1][3], b0, b1);
        }
    }

    // ---- epi2: u = relu(acc+bx1); xw = u.Wx2; tig0 lanes do their rows' aggs ----
    #pragma unroll
    for (int ch=0;ch<2;ch++){
        float px0 = 0.f, px1 = 0.f;
        #pragma unroll
        for (int nt=0;nt<9;nt++){
            int cb = nt*8 + 2*tig;
            float2 bb = *reinterpret_cast<const float2*>(V->bx1v + cb);
            float2 wx = *reinterpret_cast<const float2*>(V->Wx2v + cb);
            float u0 = fmaxf(acc[ch][nt][0] + bb.x, 0.f);
            float u1 = fmaxf(acc[ch][nt][1] + bb.y, 0.f);
            float u2 = fmaxf(acc[ch][nt][2] + bb.x, 0.f);
            float u3 = fmaxf(acc[ch][nt][3] + bb.y, 0.f);
            px0 = fmaf(u0, wx.x, fmaf(u1, wx.y, px0));
            px1 = fmaf(u2, wx.x, fmaf(u3, wx.y, px1));
        }
        px0 += __shfl_xor_sync(0xffffffffu, px0, 1);
        px0 += __shfl_xor_sync(0xffffffffu, px0, 2);
        px1 += __shfl_xor_sync(0xffffffffu, px1, 1);
        px1 += __shfl_xor_sync(0xffffffffu, px1, 2);
        if (tig == 0){
            int jl = r0 + ch*16 + g;
            float4 pj = reinterpret_cast<const float4*>(p)[b*NSEQ + jl];
            agg0 += fminf(fmaxf((pis4.x - pj.x)*px0, -100.f), 100.f);
            agg1 += fminf(fmaxf((pis4.y - pj.y)*px0, -100.f), 100.f);
            agg2 += fminf(fmaxf((pis4.z - pj.z)*px0, -100.f), 100.f);
            agg3 += fminf(fmaxf((pis4.w - pj.w)*px0, -100.f), 100.f);
            float4 ph = reinterpret_cast<const float4*>(p)[b*NSEQ + jl + 8];
            agg0 += fminf(fmaxf((pis4.x - ph.x)*px1, -100.f), 100.f);
            agg1 += fminf(fmaxf((pis4.y - ph.y)*px1, -100.f), 100.f);
            agg2 += fminf(fmaxf((pis4.z - ph.z)*px1, -100.f), 100.f);
            agg3 += fminf(fmaxf((pis4.w - ph.w)*px1, -100.f), 100.f);
        }
    }

    // ---- magg: reduce colsum over g-lanes, atomic into V->mg ----
    #pragma unroll
    for (int nt=0;nt<9;nt++)
        #pragma unroll
        for (int d=0;d<2;d++){
            float v = colsum[nt][d];
            v += __shfl_xor_sync(0xffffffffu, v, 4);
            v += __shfl_xor_sync(0xffffffffu, v, 8);
            v += __shfl_xor_sync(0xffffffffu, v, 16);
            if (g == 0) atomicAdd(&V->mg[nt*8 + 2*tig + d], v);
        }
    // ---- agg reduce across warps ----
    {
        float s0=wsum(agg0), s1=wsum(agg1), s2=wsum(agg2), s3=wsum(agg3);
        if (lane==0){ V->aggred[wid][0]=s0; V->aggred[wid][1]=s1; V->aggred[wid][2]=s2; V->aggred[wid][3]=s3; }
    }
    __syncthreads();
    if (tid < HDIM) d_magg[row*HDIM + tid] = V->mg[tid];
    if (tid < 4){
        float s = 0.f;
        #pragma unroll
        for (int w=0;w<8;w++) s += V->aggred[w][tid];
        out_p[row*4 + tid] = V->pis[tid] + (s * (1.f/256.f)) * 0.001f;
    }
}

// ---------------- h-path: y0 = [h,magg,s] @ Wh1 + bh1 (64 rows/block, tiled) ----
// also accumulates per-channel sum/sumsq for BN2 into d_bn2acc
__global__ __launch_bounds__(256) void k_y0(
    const float* __restrict__ h, const float* __restrict__ s,
    const float* __restrict__ Wh1, const float* __restrict__ bh1)
{
    extern __shared__ float ysm[];
    float* Ws   = ysm;                 // 157*72
    float* hinS = ysm + 157*HDIM;      // 64 rows, pitch 161
    int t = threadIdx.x;
    int row0 = blockIdx.x * 64;
    for (int idx = t; idx < 157*HDIM; idx += 256) Ws[idx] = Wh1[idx];
    for (int idx = t; idx < 64*HDIM; idx += 256){
        int r = idx / HDIM, c = idx - r*HDIM;
        hinS[r*161 + c]        = h[(row0+r)*HDIM + c];
        hinS[r*161 + HDIM + c] = d_magg[(row0+r)*HDIM + c];
    }
    for (int idx = t; idx < 64*SDIM; idx += 256){
        int r = idx / SDIM, c = idx - r*SDIM;
        hinS[r*161 + 2*HDIM + c] = s[(row0+r)*SDIM + c];
    }
    __syncthreads();
    int tr = t & 31, cg = t >> 5;
    int c0 = cg*9;
    float acc0[9], acc1[9];
    #pragma unroll
    for (int m=0;m<9;m++){ float bv = bh1[c0+m]; acc0[m] = bv; acc1[m] = bv; }
    const float* h0p = hinS + tr*161;
    const float* h1p = hinS + (tr+32)*161;
    #pragma unroll 4
    for (int k=0;k<157;k++){
        float x0 = h0p[k], x1 = h1p[k];
        const float* wr = Ws + k*HDIM + c0;
        #pragma unroll
        for (int m=0;m<9;m++){ float w = wr[m]; acc0[m] = fmaf(x0,w,acc0[m]); acc1[m] = fmaf(x1,w,acc1[m]); }
    }
    #pragma unroll
    for (int m=0;m<9;m++){
        d_y0[(row0+tr)*HDIM + c0+m]    = acc0[m];
        d_y0[(row0+tr+32)*HDIM + c0+m] = acc1[m];
        float sv = acc0[m] + acc1[m];
        float qv = acc0[m]*acc0[m] + acc1[m]*acc1[m];
        sv = wsum(sv);
        qv = wsum(qv);
        if (tr == 0){
            atomicAdd(&d_bn2acc[c0+m], sv);
            atomicAdd(&d_bn2acc[HDIM + c0+m], qv);
        }
    }
}

// ---------------- BN2 finalize ----------------
__global__ void k_bn2f(const float* __restrict__ gh, const float* __restrict__ bh){
    int c = threadIdx.x;
    if (c >= HDIM) return;
    float mu  = d_bn2acc[c] / 4096.f;
    float var = d_bn2acc[HDIM + c] / 4096.f - mu*mu;
    float sc  = gh[c] * rsqrtf(var + 1e-5f);
    d_bn2[c]        = sc;
    d_bn2[HDIM + c] = bh[c] - mu*sc;
}

// ---------------- h_out = h + relu(bn2(y0)) @ Wh2 + bh2 (64 rows/block) ----------
__global__ __launch_bounds__(256) void k_hout(
    const float* __restrict__ h, const float* __restrict__ Wh2,
    const float* __restrict__ bh2, float* __restrict__ out_h)
{
    __shared__ float Ws[HDIM*HDIM];
    __shared__ float yrS[64*73];
    int t = threadIdx.x;
    int row0 = blockIdx.x * 64;
    for (int idx=t; idx<HDIM*HDIM; idx+=256) Ws[idx] = Wh2[idx];
    for (int idx=t; idx<64*HDIM; idx+=256){
        int r = idx / HDIM, c = idx - r*HDIM;
        yrS[r*73 + c] = fmaxf(fmaf(d_y0[(row0+r)*HDIM + c], d_bn2[c], d_bn2[HDIM + c]), 0.f);
    }
    __syncthreads();
    int tr = t & 31, cg = t >> 5;
    int c0 = cg*9;
    float acc0[9], acc1[9];
    #pragma unroll
    for (int m=0;m<9;m++){ float bv = bh2[c0+m]; acc0[m] = bv; acc1[m] = bv; }
    const float* y0p = yrS + tr*73;
    const float* y1p = yrS + (tr+32)*73;
    #pragma unroll 4
    for (int k=0;k<HDIM;k++){
        float x0 = y0p[k], x1 = y1p[k];
        const float* wr = Ws + k*HDIM + c0;
        #pragma unroll
        for (int m=0;m<9;m++){ float w = wr[m]; acc0[m] = fmaf(x0,w,acc0[m]); acc1[m] = fmaf(x1,w,acc1[m]); }
    }
    #pragma unroll
    for (int m=0;m<9;m++){
        out_h[(row0+tr)*HDIM + c0+m]    = h[(row0+tr)*HDIM + c0+m]    + acc0[m];
        out_h[(row0+tr+32)*HDIM + c0+m] = h[(row0+tr+32)*HDIM + c0+m] + acc1[m];
    }
}

// ---------------- launch ----------------
extern "C" void kernel_launch(void* const* d_in, const int* in_sizes, int n_in,
                              void* d_out, int out_size){
    const float* h   = (const float*)d_in[0];
    const float* p   = (const float*)d_in[1];
    const float* s   = (const float*)d_in[2];
    const float* We1 = (const float*)d_in[3];
    const float* g1  = (const float*)d_in[4];
    const float* b1  = (const float*)d_in[5];
    const float* We2 = (const float*)d_in[6];
    const float* be2 = (const float*)d_in[7];
    const float* Wm  = (const float*)d_in[8];
    const float* bm  = (const float*)d_in[9];
    const float* Wx1 = (const float*)d_in[10];
    const float* bx1 = (const float*)d_in[11];
    const float* Wx2 = (const float*)d_in[12];
    const float* Wh1 = (const float*)d_in[13];
    const float* bh1 = (const float*)d_in[14];
    const float* gh  = (const float*)d_in[15];
    const float* bh  = (const float*)d_in[16];
    const float* Wh2 = (const float*)d_in[17];
    const float* bh2 = (const float*)d_in[18];
    float* out   = (float*)d_out;
    float* out_h = out;                 // (B,N,H) first
    float* out_p = out + ROWS*HDIM;     // then (B,N,4)

    const int y0smem = (157*HDIM + 64*161) * 4;
    cudaFuncSetAttribute(k_main, cudaFuncAttributeMaxDynamicSharedMemorySize, KSMEM_TOTAL);
    cudaFuncSetAttribute(k_y0,   cudaFuncAttributeMaxDynamicSharedMemorySize, y0smem);

    k_zero <<<8, 256>>>(We2, Wx1);
    k_geom <<<dim3(NSEQ, BATCH), NSEQ>>>(p);
    k_AB   <<<ROWS/8, 256>>>(h, We1);
    k_mom  <<<dim3(HDIM, BATCH), 256>>>();
    k_bn1  <<<1, 128>>>(We1, g1, b1);
    k_main <<<dim3(NSEQ, BATCH), 256, KSMEM_TOTAL>>>(p, be2, Wm, bm, bx1, Wx2, out_p);
    k_y0   <<<ROWS/64, 256, y0smem>>>(h, s, Wh1, bh1);
    k_bn2f <<<1, 128>>>(gh, bh);
    k_hout <<<ROWS/64, 256>>>(h, Wh2, bh2, out_h);
}